// round 11
// baseline (speedup 1.0000x reference)
#include <cuda_runtime.h>
#include <cuda_bf16.h>
#include <cstdint>
#include <math.h>

// ---------------- problem constants ----------------
#define CAMS   4
#define DSLICE 4      // D = NDISP/2
#define NDISP  8
#define IH     640
#define IW     1280
#define FH     320
#define FW     640
#define C1     32
#define HO     256
#define WO     256
#define CF     128    // fused cost channels
#define C2     64
#define C3     32

#define PK1    (CF + 8)    // padded K (elements) conv1
#define PK2    (C2 + 8)    // padded K conv2

// ---------------- scratch (static device memory; no allocs) ----------------
__device__ float g_feat [(size_t)CAMS*FH*FW*C1];              // [cam][y][x][c]
__device__ float g_warp [(size_t)CAMS*DSLICE*FH*FW*C1];       // [cam][d][y][x][c]
__device__ __nv_bfloat16 g_costs_h[(size_t)DSLICE*HO*WO*CF];  // hi plane, [d][h][w][c]
__device__ __nv_bfloat16 g_costs_l[(size_t)DSLICE*HO*WO*CF];  // lo plane
__device__ __nv_bfloat16 g_x1_h  [(size_t)DSLICE*HO*WO*C2];
__device__ __nv_bfloat16 g_x1_l  [(size_t)DSLICE*HO*WO*C2];
__device__ float g_x2   [(size_t)DSLICE*HO*WO*C3];
__device__ float g_x3   [(size_t)DSLICE*HO*WO];
__device__ __nv_bfloat16 g_wB1[27*2*C2*PK1];   // [tap][hi/lo][n][PK1]
__device__ __nv_bfloat16 g_wB2[27*2*C3*PK2];   // [tap][hi/lo][n][PK2]

// =====================================================================
// helpers
// =====================================================================
__device__ __forceinline__ uint32_t smem_u32(const void* p) {
    uint32_t a;
    asm("{ .reg .u64 t; cvta.to.shared.u64 t, %1; cvt.u32.u64 %0, t; }" : "=r"(a) : "l"(p));
    return a;
}
__device__ __forceinline__ uint32_t lds32(uint32_t addr) {
    uint32_t r;
    asm volatile("ld.shared.b32 %0, [%1];" : "=r"(r) : "r"(addr));
    return r;
}
__device__ __forceinline__ void cp_async16(uint32_t dst, const void* src, bool valid) {
    int sz = valid ? 16 : 0;
    asm volatile("cp.async.cg.shared.global [%0], [%1], 16, %2;"
                 :: "r"(dst), "l"(src), "r"(sz) : "memory");
}
__device__ __forceinline__ void cp_commit() {
    asm volatile("cp.async.commit_group;" ::: "memory");
}
__device__ __forceinline__ void cp_wait0() {
    asm volatile("cp.async.wait_group 0;" ::: "memory");
}
__device__ __forceinline__ void mma_bf16(float& d0, float& d1, float& d2, float& d3,
                                         uint32_t a0, uint32_t a1, uint32_t a2, uint32_t a3,
                                         uint32_t b0, uint32_t b1)
{
    asm volatile(
        "mma.sync.aligned.m16n8k16.row.col.f32.bf16.bf16.f32 "
        "{%0,%1,%2,%3}, {%4,%5,%6,%7}, {%8,%9}, {%0,%1,%2,%3};"
        : "+f"(d0), "+f"(d1), "+f"(d2), "+f"(d3)
        : "r"(a0), "r"(a1), "r"(a2), "r"(a3), "r"(b0), "r"(b1));
}
// pack two floats into bf16x2 hi pair + residual bf16x2 lo pair
__device__ __forceinline__ void split2(float x0, float x1, uint32_t& hi, uint32_t& lo)
{
    __nv_bfloat16 h0 = __float2bfloat16(x0);
    __nv_bfloat16 h1 = __float2bfloat16(x1);
    float r0 = x0 - __bfloat162float(h0);
    float r1 = x1 - __bfloat162float(h1);
    __nv_bfloat162 hp = __halves2bfloat162(h0, h1);
    __nv_bfloat162 lp = __halves2bfloat162(__float2bfloat16(r0), __float2bfloat16(r1));
    hi = *(uint32_t*)&hp;
    lo = *(uint32_t*)&lp;
}

// ---------------- K1: conv2d 3->32 s2 + relu (grid.z<4) fused with weight prep (grid.z==4) ----
__global__ void k_feat4w(const float* __restrict__ c0, const float* __restrict__ c1,
                         const float* __restrict__ c2, const float* __restrict__ c3,
                         const float* __restrict__ w,
                         const float* __restrict__ w_fusion, const float* __restrict__ w_reg1)
{
    int tid = threadIdx.y * 16 + threadIdx.x;
    int zi  = blockIdx.z;

    if (zi == 4) {
        int idx0   = (blockIdx.y * (FW / 16) + blockIdx.x) * 256 + tid;
        int stride = (FW / 16) * (FH / 16) * 256;
        for (int i = idx0; i < 27 * C2 * CF; i += stride) {
            int k = i % CF;
            int n = (i / CF) % C2;
            int t = i / (CF * C2);
            int kw = t % 3, kh = (t / 3) % 3, kd = t / 9;
            float v = w_fusion[((((size_t)n * CF + k) * 3 + kd) * 3 + kh) * 3 + kw];
            __nv_bfloat16 h = __float2bfloat16(v);
            __nv_bfloat16 l = __float2bfloat16(v - __bfloat162float(h));
            g_wB1[((size_t)(t * 2 + 0) * C2 + n) * PK1 + k] = h;
            g_wB1[((size_t)(t * 2 + 1) * C2 + n) * PK1 + k] = l;
        }
        for (int i = idx0; i < 27 * C3 * C2; i += stride) {
            int k = i % C2;
            int n = (i / C2) % C3;
            int t = i / (C2 * C3);
            int kw = t % 3, kh = (t / 3) % 3, kd = t / 9;
            float v = w_reg1[((((size_t)n * C2 + k) * 3 + kd) * 3 + kh) * 3 + kw];
            __nv_bfloat16 h = __float2bfloat16(v);
            __nv_bfloat16 l = __float2bfloat16(v - __bfloat162float(h));
            g_wB2[((size_t)(t * 2 + 0) * C3 + n) * PK2 + k] = h;
            g_wB2[((size_t)(t * 2 + 1) * C3 + n) * PK2 + k] = l;
        }
        return;
    }

    __shared__ float ws[27 * 32];
    for (int i = tid; i < 864; i += 256) {
        int k = i >> 5, oc = i & 31;
        ws[i] = w[oc * 27 + k];
    }
    __syncthreads();

    const float* cam = (zi == 0) ? c0 : (zi == 1) ? c1 : (zi == 2) ? c2 : c3;
    int ow = blockIdx.x * 16 + threadIdx.x;
    int oh = blockIdx.y * 16 + threadIdx.y;

    float v[27];
#pragma unroll
    for (int ic = 0; ic < 3; ic++)
#pragma unroll
        for (int kh = 0; kh < 3; kh++)
#pragma unroll
            for (int kw = 0; kw < 3; kw++) {
                int iy = 2 * oh + kh - 1;
                int ix = 2 * ow + kw - 1;
                float t = 0.f;
                if (iy >= 0 && iy < IH && ix >= 0 && ix < IW)
                    t = cam[(size_t)ic * IH * IW + (size_t)iy * IW + ix];
                v[ic * 9 + kh * 3 + kw] = t;
            }

    float4 acc[8];
#pragma unroll
    for (int q = 0; q < 8; q++) acc[q] = make_float4(0.f, 0.f, 0.f, 0.f);
    const float4* ws4 = (const float4*)ws;
#pragma unroll
    for (int k = 0; k < 27; k++) {
        float vv = v[k];
#pragma unroll
        for (int q = 0; q < 8; q++) {
            float4 wv = ws4[k * 8 + q];
            acc[q].x += vv * wv.x;  acc[q].y += vv * wv.y;
            acc[q].z += vv * wv.z;  acc[q].w += vv * wv.w;
        }
    }
    float4* o = (float4*)(g_feat + ((size_t)zi * FH * FW + (size_t)oh * FW + ow) * C1);
#pragma unroll
    for (int q = 0; q < 8; q++) {
        float4 r = acc[q];
        r.x = fmaxf(r.x, 0.f); r.y = fmaxf(r.y, 0.f);
        r.z = fmaxf(r.z, 0.f); r.w = fmaxf(r.w, 0.f);
        o[q] = r;
    }
}

// ---------------- K2: grid_sample, warp-cooperative, 2 d-slices per thread ----------------
__global__ void __launch_bounds__(256)
k_warp(const float* __restrict__ grids)
{
    int tid = threadIdx.x;
    int c   = tid & 7;
    int pid = tid >> 3;
    int pos = blockIdx.x * 32 + pid;
    int d0  = blockIdx.y;
    int cam = blockIdx.z;
    int y = pos / FW, x = pos % FW;

    const float* fb = g_feat + (size_t)cam * FH * FW * C1 + c * 4;

#pragma unroll
    for (int s = 0; s < 2; s++) {
        int d = d0 + s * 2;
        const float* g = grids + ((((size_t)cam * DSLICE + d) * FH + y) * FW + x) * 2;
        float fx = (g[0] + 1.f) * (FW * 0.5f) - 0.5f;
        float fy = (g[1] + 1.f) * (FH * 0.5f) - 0.5f;
        float x0f = floorf(fx), y0f = floorf(fy);
        float wx = fx - x0f,   wy = fy - y0f;
        int x0 = (int)x0f, y0 = (int)y0f;
        int x1 = x0 + 1,   y1 = y0 + 1;
        float vx0 = (x0 >= 0 && x0 < FW) ? 1.f : 0.f;
        float vx1 = (x1 >= 0 && x1 < FW) ? 1.f : 0.f;
        float vy0 = (y0 >= 0 && y0 < FH) ? 1.f : 0.f;
        float vy1 = (y1 >= 0 && y1 < FH) ? 1.f : 0.f;
        float w00 = (1.f - wx) * (1.f - wy) * vx0 * vy0;
        float w01 = wx * (1.f - wy) * vx1 * vy0;
        float w10 = (1.f - wx) * wy * vx0 * vy1;
        float w11 = wx * wy * vx1 * vy1;
        int x0c = min(max(x0, 0), FW - 1), x1c = min(max(x1, 0), FW - 1);
        int y0c = min(max(y0, 0), FH - 1), y1c = min(max(y1, 0), FH - 1);

        float4 a = *(const float4*)(fb + ((size_t)y0c * FW + x0c) * C1);
        float4 b = *(const float4*)(fb + ((size_t)y0c * FW + x1c) * C1);
        float4 e = *(const float4*)(fb + ((size_t)y1c * FW + x0c) * C1);
        float4 f = *(const float4*)(fb + ((size_t)y1c * FW + x1c) * C1);

        float4 r;
        r.x = w00 * a.x + w01 * b.x + w10 * e.x + w11 * f.x;
        r.y = w00 * a.y + w01 * b.y + w10 * e.y + w11 * f.y;
        r.z = w00 * a.z + w01 * b.z + w10 * e.z + w11 * f.z;
        r.w = w00 * a.w + w01 * b.w + w10 * e.w + w11 * f.w;
        *(float4*)(g_warp + ((size_t)(cam * DSLICE + d) * FH * FW + pos) * C1 + c * 4) = r;
    }
}

// ---------------- K3: antialiased resize, warp-cooperative, bf16 hi/lo output ----------------
__global__ void __launch_bounds__(256)
k_resize()
{
    int tid  = threadIdx.x;
    int c    = tid & 7;
    int pid  = tid >> 3;
    int opos = blockIdx.x * 32 + pid;
    int ho   = opos >> 8;
    int wo   = opos & 255;
    int d    = blockIdx.y;
    int cam  = blockIdx.z;

    float sy = (ho + 0.5f) * 1.25f - 0.5f;
    int jy0 = max((int)ceilf(sy - 1.25f), 0);
    int jy1 = min((int)floorf(sy + 1.25f), FH - 1);
    float wyv[4]; int ny = jy1 - jy0 + 1;
    float sumy = 0.f;
    for (int i = 0; i < ny; i++) {
        float w = fmaxf(1.f - fabsf(sy - (float)(jy0 + i)) * 0.8f, 0.f);
        wyv[i] = w; sumy += w;
    }
    for (int i = 0; i < ny; i++) wyv[i] /= sumy;

    float sx = (wo + 0.5f) * 2.5f - 0.5f;
    int jx0 = max((int)ceilf(sx - 2.5f), 0);
    int jx1 = min((int)floorf(sx + 2.5f), FW - 1);
    float wxv[6]; int nx = jx1 - jx0 + 1;
    float sumx = 0.f;
    for (int i = 0; i < nx; i++) {
        float w = fmaxf(1.f - fabsf(sx - (float)(jx0 + i)) * 0.4f, 0.f);
        wxv[i] = w; sumx += w;
    }
    for (int i = 0; i < nx; i++) wxv[i] /= sumx;

    float4 acc = make_float4(0.f, 0.f, 0.f, 0.f);
    const float* base = g_warp + (size_t)(cam * DSLICE + d) * FH * FW * C1 + c * 4;
    for (int iy = 0; iy < ny; iy++) {
        const float* rowb = base + (size_t)(jy0 + iy) * FW * C1;
        for (int ix = 0; ix < nx; ix++) {
            float wgt = wyv[iy] * wxv[ix];
            float4 t = *(const float4*)(rowb + (size_t)(jx0 + ix) * C1);
            acc.x += wgt * t.x; acc.y += wgt * t.y;
            acc.z += wgt * t.z; acc.w += wgt * t.w;
        }
    }
    size_t obase = (((size_t)d * HO + ho) * WO + wo) * CF + cam * C1 + c * 4;
    uint32_t h0, l0, h1, l1;
    split2(acc.x, acc.y, h0, l0);
    split2(acc.z, acc.w, h1, l1);
    *(uint2*)(g_costs_h + obase) = make_uint2(h0, h1);
    *(uint2*)(g_costs_l + obase) = make_uint2(l0, l1);
}

// ---------------- K4: conv3d 3x3x3 pad1 + relu, mma.sync bf16 split, full-row M=256 --------
// 256 threads / 8 warps. Block covers one full (oh,od) output row (M=256 positions).
// A single-buffered (258-position halo, restaged per (kd,kh)); B tap DOUBLE-buffered so
// the per-item B wait hides under the previous item's compute.
// conv1: MI=4, NWN=2 (warp M64xN32). conv2: MI=2, NWN=1 (warp M32xN32).
template<int CIN, int COUT, int MI, int NWN, bool OBF>
__global__ void __launch_bounds__(256)
k_conv3d_mma(const __nv_bfloat16* __restrict__ in_h, const __nv_bfloat16* __restrict__ in_l,
             const __nv_bfloat16* __restrict__ wB,
             __nv_bfloat16* __restrict__ out_h, __nv_bfloat16* __restrict__ out_l,
             float* __restrict__ out_f)
{
    constexpr int NT   = 256;
    constexpr int PK   = CIN + 8;
    constexpr int PKB  = PK * 2;             // bytes per smem row
    constexpr int SA   = 258 * PKB;          // one A plane (hi or lo), full-row halo
    constexpr int TB   = 2 * COUT * PKB;     // B tap (hi + lo)
    constexpr int NJ   = (COUT / NWN) / 8;   // 4
    constexpr int KST  = CIN / 16;           // k-steps per item
    constexpr int CH   = CIN / 8;            // 16B chunks per A row per plane

    extern __shared__ char dsm[];
    const uint32_t sBase = smem_u32(dsm);
    const uint32_t sA  = sBase;              // [A(hi+lo) | B0 | B1]
    const uint32_t sB0 = sBase + 2 * SA;

    int tid  = threadIdx.x;
    int wid  = tid >> 5, lane = tid & 31;
    int gid  = lane >> 2, tig = lane & 3;
    int wM   = wid / NWN;
    int wN   = wid % NWN;
    int oh   = blockIdx.x, od = blockIdx.y;

    // ---- build valid (kd,kh) list ----
    int zdv[9], zhv[9], t9v[9];
    int nv = 0;
    for (int kd = 0; kd < 3; kd++) {
        int zd = od + kd - 1;
        if (zd < 0 || zd >= DSLICE) continue;
        for (int kh = 0; kh < 3; kh++) {
            int zh = oh + kh - 1;
            if (zh < 0 || zh >= HO) continue;
            zdv[nv] = zd; zhv[nv] = zh; t9v[nv] = kd * 3 + kh;
            nv++;
        }
    }
    int nitems = nv * 3;

    float acc[MI][NJ][4];
#pragma unroll
    for (int mi = 0; mi < MI; mi++)
#pragma unroll
        for (int nj = 0; nj < NJ; nj++)
#pragma unroll
            for (int cc = 0; cc < 4; cc++) acc[mi][nj][cc] = 0.f;

    auto stage_A = [&](int ai) {
        size_t inoff = ((size_t)zdv[ai] * HO + zhv[ai]) * WO * CIN;
        for (int i = tid; i < 258 * CH; i += NT) {
            int r = i / CH, g = i % CH;
            int p = r - 1;                   // position -1 .. 256
            bool v = (p >= 0 && p < WO);
            int pc = v ? p : 0;
            size_t so = inoff + (size_t)pc * CIN + g * 8;
            uint32_t doff = (uint32_t)r * PKB + g * 16;
            cp_async16(sA + doff,      in_h + so, v);
            cp_async16(sA + SA + doff, in_l + so, v);
        }
    };
    auto stage_B = [&](int slot, int j) {
        int t = t9v[j / 3] * 3 + (j % 3);
        const char* src = (const char*)(wB + (size_t)t * COUT * PK * 2);
        uint32_t dB = sB0 + slot * TB;
        for (int i = tid; i < TB / 16; i += NT)
            cp_async16(dB + i * 16, src + i * 16, true);
    };

    // prologue: stage item 0 fully
    stage_A(0);
    stage_B(0, 0);
    cp_commit();
    cp_wait0();
    __syncthreads();

    for (int j = 0; j < nitems; j++) {
        int jn = j + 1;
        // issue next B tap into the other slot; it completes under this item's compute
        if (jn < nitems) {
            stage_B(jn & 1, jn);
            cp_commit();
        }

        // ---- compute item j ----
        int q = j % 3;
        uint32_t aB0 = sA + (uint32_t)(q + wM * (MI * 16) + gid) * PKB + tig * 4;
        uint32_t bB0 = sB0 + (uint32_t)(j & 1) * TB + (uint32_t)(wN * 32 + gid) * PKB + tig * 4;
#pragma unroll
        for (int ks = 0; ks < KST; ks++) {
            uint32_t ko = (uint32_t)ks * 32;
            uint32_t ah[MI][4], al[MI][4];
            uint32_t bh[NJ][2], bl[NJ][2];
#pragma unroll
            for (int mi = 0; mi < MI; mi++) {
                uint32_t a = aB0 + mi * 16 * PKB + ko;
                ah[mi][0] = lds32(a);
                ah[mi][1] = lds32(a + 8 * PKB);
                ah[mi][2] = lds32(a + 16);
                ah[mi][3] = lds32(a + 8 * PKB + 16);
                uint32_t b = a + SA;
                al[mi][0] = lds32(b);
                al[mi][1] = lds32(b + 8 * PKB);
                al[mi][2] = lds32(b + 16);
                al[mi][3] = lds32(b + 8 * PKB + 16);
            }
#pragma unroll
            for (int nj = 0; nj < NJ; nj++) {
                uint32_t bb = bB0 + nj * 8 * PKB + ko;
                bh[nj][0] = lds32(bb);
                bh[nj][1] = lds32(bb + 16);
                bl[nj][0] = lds32(bb + COUT * PKB);
                bl[nj][1] = lds32(bb + COUT * PKB + 16);
            }
            // split-outermost: consecutive mmas hit different accumulators
#pragma unroll
            for (int nj = 0; nj < NJ; nj++)
#pragma unroll
                for (int mi = 0; mi < MI; mi++)
                    mma_bf16(acc[mi][nj][0], acc[mi][nj][1], acc[mi][nj][2], acc[mi][nj][3],
                             ah[mi][0], ah[mi][1], ah[mi][2], ah[mi][3],
                             bh[nj][0], bh[nj][1]);
#pragma unroll
            for (int nj = 0; nj < NJ; nj++)
#pragma unroll
                for (int mi = 0; mi < MI; mi++)
                    mma_bf16(acc[mi][nj][0], acc[mi][nj][1], acc[mi][nj][2], acc[mi][nj][3],
                             ah[mi][0], ah[mi][1], ah[mi][2], ah[mi][3],
                             bl[nj][0], bl[nj][1]);
#pragma unroll
            for (int nj = 0; nj < NJ; nj++)
#pragma unroll
                for (int mi = 0; mi < MI; mi++)
                    mma_bf16(acc[mi][nj][0], acc[mi][nj][1], acc[mi][nj][2], acc[mi][nj][3],
                             al[mi][0], al[mi][1], al[mi][2], al[mi][3],
                             bh[nj][0], bh[nj][1]);
        }

        if (jn < nitems) {
            if (jn % 3 == 0) {
                __syncthreads();            // all warps done reading A before restage
                stage_A(jn / 3);
                cp_commit();
            }
            cp_wait0();                      // B(jn) (+A when restaged) complete
            __syncthreads();                 // visibility across warps
        }
    }

    // ---- epilogue: relu + store ----
#pragma unroll
    for (int mi = 0; mi < MI; mi++) {
        int row = wM * (MI * 16) + mi * 16 + gid;
        size_t base0 = (((size_t)od * HO + oh) * WO + row) * COUT;
        size_t base1 = base0 + 8 * COUT;      // row + 8
#pragma unroll
        for (int nj = 0; nj < NJ; nj++) {
            int col = wN * 32 + nj * 8 + tig * 2;
            float v00 = fmaxf(acc[mi][nj][0], 0.f);
            float v01 = fmaxf(acc[mi][nj][1], 0.f);
            float v10 = fmaxf(acc[mi][nj][2], 0.f);
            float v11 = fmaxf(acc[mi][nj][3], 0.f);
            if (OBF) {
                uint32_t h0, l0, h1, l1;
                split2(v00, v01, h0, l0);
                split2(v10, v11, h1, l1);
                *(uint32_t*)(out_h + base0 + col) = h0;
                *(uint32_t*)(out_l + base0 + col) = l0;
                *(uint32_t*)(out_h + base1 + col) = h1;
                *(uint32_t*)(out_l + base1 + col) = l1;
            } else {
                *(float2*)(out_f + base0 + col) = make_float2(v00, v01);
                *(float2*)(out_f + base1 + col) = make_float2(v10, v11);
            }
        }
    }
}

// ---------------- K5: conv3d 32->1 (no relu), smem-tiled ----------------
__global__ void __launch_bounds__(256)
k_reg2(const float* __restrict__ w2)
{
    __shared__ float ws_t[27 * 32];                 // [k27][ic32]
    __shared__ float tile[10][34][32];              // [zh][zw][c]
    int tx = threadIdx.x & 31;
    int ty = threadIdx.x >> 5;
    int tid = threadIdx.x;
    for (int i = tid; i < 864; i += 256) {
        int ic = i / 27, k = i % 27;
        ws_t[k * 32 + ic] = w2[i];
    }

    int ow0 = blockIdx.x * 32;
    int oh0 = blockIdx.y * 8;
    int od  = blockIdx.z;
    int ow = ow0 + tx, oh = oh0 + ty;

    float acc = 0.f;
    for (int kd = 0; kd < 3; kd++) {
        int zd = od + kd - 1;
        if (zd < 0 || zd >= DSLICE) continue;
        __syncthreads();
        for (int i = tid; i < 10 * 34 * 8; i += 256) {
            int g  = i & 7;
            int zw = (i >> 3) % 34 + ow0 - 1;
            int zh = (i >> 3) / 34 + oh0 - 1;
            bool v = (zw >= 0 && zw < WO && zh >= 0 && zh < HO);
            int zwc = v ? zw : 0, zhc = v ? zh : 0;
            const float* src = g_x2 + (((size_t)zd * HO + zhc) * WO + zwc) * C3 + g * 4;
            cp_async16(smem_u32(&tile[(i >> 3) / 34][(i >> 3) % 34][g * 4]), src, v);
        }
        cp_commit();
        cp_wait0();
        __syncthreads();

#pragma unroll
        for (int kh = 0; kh < 3; kh++) {
#pragma unroll
            for (int kw = 0; kw < 3; kw++) {
                int k = kd * 9 + kh * 3 + kw;
                const float4* p  = (const float4*)&tile[ty + kh][tx + kw][0];
                const float4* wv = (const float4*)&ws_t[k * 32];
#pragma unroll
                for (int qq = 0; qq < 8; qq++) {
                    float4 a = p[qq], b = wv[qq];
                    acc += a.x * b.x + a.y * b.y + a.z * b.z + a.w * b.w;
                }
            }
        }
    }
    g_x3[((size_t)od * HO + oh) * WO + ow] = acc;
}

// ---------------- K6: D-resize 4->8 + softmax + expectation ----------------
__global__ void k_final(float* __restrict__ outp)
{
    int pos = blockIdx.x * 256 + threadIdx.x;
    float v[4];
#pragma unroll
    for (int d = 0; d < 4; d++) v[d] = g_x3[(size_t)d * (HO * WO) + pos];

    float y[8];
#pragma unroll
    for (int o = 0; o < 8; o++) {
        float s = 0.5f * o - 0.25f;
        int j0 = max(0, (int)ceilf(s - 1.f));
        int j1 = min(3, (int)floorf(s + 1.f));
        float acc = 0.f, wsum = 0.f;
        for (int j = j0; j <= j1; j++) {
            float w = fmaxf(1.f - fabsf(s - (float)j), 0.f);
            acc += w * v[j]; wsum += w;
        }
        y[o] = acc / wsum;
    }
    float m = y[0];
#pragma unroll
    for (int o = 1; o < 8; o++) m = fmaxf(m, y[o]);
    float esum = 0.f, dsum = 0.f;
#pragma unroll
    for (int o = 0; o < 8; o++) {
        float e = expf(y[o] - m);
        esum += e;
        dsum += e * (float)o;
    }
    outp[pos] = dsum / esum;
}

// ---------------- host launch ----------------
extern "C" void kernel_launch(void* const* d_in, const int* in_sizes, int n_in,
                              void* d_out, int out_size)
{
    const float* cams[4] = { (const float*)d_in[0], (const float*)d_in[1],
                             (const float*)d_in[2], (const float*)d_in[3] };
    const float* grids    = (const float*)d_in[4];
    const float* w_feat   = (const float*)d_in[5];
    const float* w_fusion = (const float*)d_in[6];
    const float* w_reg1   = (const float*)d_in[7];
    const float* w_reg2   = (const float*)d_in[8];
    float* out = (float*)d_out;

    __nv_bfloat16 *p_wB1, *p_wB2, *p_ch, *p_cl, *p_x1h, *p_x1l;
    float* p_x2;
    cudaGetSymbolAddress((void**)&p_x2,  g_x2);
    cudaGetSymbolAddress((void**)&p_wB1, g_wB1);
    cudaGetSymbolAddress((void**)&p_wB2, g_wB2);
    cudaGetSymbolAddress((void**)&p_ch,  g_costs_h);
    cudaGetSymbolAddress((void**)&p_cl,  g_costs_l);
    cudaGetSymbolAddress((void**)&p_x1h, g_x1_h);
    cudaGetSymbolAddress((void**)&p_x1l, g_x1_l);

    // full-row M=256: A(hi+lo, 258 halo) + 2 B slots (hi+lo each)
    const int SMEM1 = 2 * (258 * PK1 * 2) + 2 * (2 * C2 * PK1 * 2);   // 140352 + 69632 = 209984
    const int SMEM2 = 2 * (258 * PK2 * 2) + 2 * (2 * C3 * PK2 * 2);   //  74304 + 18432 =  92736
    cudaFuncSetAttribute((const void*)k_conv3d_mma<CF, C2, 4, 2, true>,
                         cudaFuncAttributeMaxDynamicSharedMemorySize, SMEM1);
    cudaFuncSetAttribute((const void*)k_conv3d_mma<C2, C3, 2, 1, false>,
                         cudaFuncAttributeMaxDynamicSharedMemorySize, SMEM2);

    // 1: feature extraction + weight prep (fused)
    k_feat4w<<<dim3(FW / 16, FH / 16, 5), dim3(16, 16)>>>(
        cams[0], cams[1], cams[2], cams[3], w_feat, w_fusion, w_reg1);

    // 2: plane sweep warp (2 d per thread)
    k_warp<<<dim3(FH * FW / 32, 2, CAMS), 256>>>(grids);

    // 3: antialiased resize -> bf16 hi/lo cost volume
    k_resize<<<dim3(HO * WO / 32, DSLICE, CAMS), 256>>>();

    // 4: conv1 (profiled launch)  5: conv2 — full-row blocks, B double-buffered
    k_conv3d_mma<CF, C2, 4, 2, true ><<<dim3(HO, DSLICE), 256, SMEM1>>>(p_ch,  p_cl,  p_wB1, p_x1h, p_x1l, nullptr);
    k_conv3d_mma<C2, C3, 2, 1, false><<<dim3(HO, DSLICE), 256, SMEM2>>>(p_x1h, p_x1l, p_wB2, nullptr, nullptr, p_x2);

    // 6: squeeze conv
    k_reg2<<<dim3(WO / 32, HO / 8, DSLICE), 256>>>(w_reg2);

    // 7: disparity regression
    k_final<<<(HO * WO) / 256, 256>>>(out);
}

// round 12
// speedup vs baseline: 1.5570x; 1.5570x over previous
#include <cuda_runtime.h>
#include <cuda_bf16.h>
#include <cstdint>
#include <math.h>

// ---------------- problem constants ----------------
#define CAMS   4
#define DSLICE 4      // D = NDISP/2
#define NDISP  8
#define IH     640
#define IW     1280
#define FH     320
#define FW     640
#define C1     32
#define HO     256
#define WO     256
#define CF     128    // fused cost channels
#define C2     64
#define C3     32

#define PK1    (CF + 8)    // padded K (elements) conv1
#define PK2    (C2 + 8)    // padded K conv2

// ---------------- scratch (static device memory; no allocs) ----------------
__device__ float g_feat [(size_t)CAMS*FH*FW*C1];              // [cam][y][x][c]
__device__ float g_warp [(size_t)CAMS*DSLICE*FH*FW*C1];       // [cam][d][y][x][c]
__device__ __nv_bfloat16 g_costs_h[(size_t)DSLICE*HO*WO*CF];  // hi plane, [d][h][w][c]
__device__ __nv_bfloat16 g_costs_l[(size_t)DSLICE*HO*WO*CF];  // lo plane
__device__ __nv_bfloat16 g_x1_h  [(size_t)DSLICE*HO*WO*C2];
__device__ __nv_bfloat16 g_x1_l  [(size_t)DSLICE*HO*WO*C2];
__device__ float g_x2   [(size_t)DSLICE*HO*WO*C3];
__device__ float g_x3   [(size_t)DSLICE*HO*WO];
__device__ __nv_bfloat16 g_wB1[27*2*C2*PK1];   // [tap][hi/lo][n][PK1]
__device__ __nv_bfloat16 g_wB2[27*2*C3*PK2];   // [tap][hi/lo][n][PK2]

// =====================================================================
// helpers
// =====================================================================
__device__ __forceinline__ uint32_t smem_u32(const void* p) {
    uint32_t a;
    asm("{ .reg .u64 t; cvta.to.shared.u64 t, %1; cvt.u32.u64 %0, t; }" : "=r"(a) : "l"(p));
    return a;
}
__device__ __forceinline__ uint32_t lds32(uint32_t addr) {
    uint32_t r;
    asm volatile("ld.shared.b32 %0, [%1];" : "=r"(r) : "r"(addr));
    return r;
}
__device__ __forceinline__ void cp_async16(uint32_t dst, const void* src, bool valid) {
    int sz = valid ? 16 : 0;
    asm volatile("cp.async.cg.shared.global [%0], [%1], 16, %2;"
                 :: "r"(dst), "l"(src), "r"(sz) : "memory");
}
__device__ __forceinline__ void cp_commit() {
    asm volatile("cp.async.commit_group;" ::: "memory");
}
__device__ __forceinline__ void cp_wait1() {
    asm volatile("cp.async.wait_group 1;" ::: "memory");
}
__device__ __forceinline__ void cp_wait0() {
    asm volatile("cp.async.wait_group 0;" ::: "memory");
}
__device__ __forceinline__ void mma_bf16(float& d0, float& d1, float& d2, float& d3,
                                         uint32_t a0, uint32_t a1, uint32_t a2, uint32_t a3,
                                         uint32_t b0, uint32_t b1)
{
    asm volatile(
        "mma.sync.aligned.m16n8k16.row.col.f32.bf16.bf16.f32 "
        "{%0,%1,%2,%3}, {%4,%5,%6,%7}, {%8,%9}, {%0,%1,%2,%3};"
        : "+f"(d0), "+f"(d1), "+f"(d2), "+f"(d3)
        : "r"(a0), "r"(a1), "r"(a2), "r"(a3), "r"(b0), "r"(b1));
}
// pack two floats into bf16x2 hi pair + residual bf16x2 lo pair
__device__ __forceinline__ void split2(float x0, float x1, uint32_t& hi, uint32_t& lo)
{
    __nv_bfloat16 h0 = __float2bfloat16(x0);
    __nv_bfloat16 h1 = __float2bfloat16(x1);
    float r0 = x0 - __bfloat162float(h0);
    float r1 = x1 - __bfloat162float(h1);
    __nv_bfloat162 hp = __halves2bfloat162(h0, h1);
    __nv_bfloat162 lp = __halves2bfloat162(__float2bfloat16(r0), __float2bfloat16(r1));
    hi = *(uint32_t*)&hp;
    lo = *(uint32_t*)&lp;
}

// ---------------- K1: conv2d 3->32 s2 + relu (grid.z<4) fused with weight prep (grid.z==4) ----
__global__ void k_feat4w(const float* __restrict__ c0, const float* __restrict__ c1,
                         const float* __restrict__ c2, const float* __restrict__ c3,
                         const float* __restrict__ w,
                         const float* __restrict__ w_fusion, const float* __restrict__ w_reg1)
{
    int tid = threadIdx.y * 16 + threadIdx.x;
    int zi  = blockIdx.z;

    if (zi == 4) {
        int idx0   = (blockIdx.y * (FW / 16) + blockIdx.x) * 256 + tid;
        int stride = (FW / 16) * (FH / 16) * 256;
        for (int i = idx0; i < 27 * C2 * CF; i += stride) {
            int k = i % CF;
            int n = (i / CF) % C2;
            int t = i / (CF * C2);
            int kw = t % 3, kh = (t / 3) % 3, kd = t / 9;
            float v = w_fusion[((((size_t)n * CF + k) * 3 + kd) * 3 + kh) * 3 + kw];
            __nv_bfloat16 h = __float2bfloat16(v);
            __nv_bfloat16 l = __float2bfloat16(v - __bfloat162float(h));
            g_wB1[((size_t)(t * 2 + 0) * C2 + n) * PK1 + k] = h;
            g_wB1[((size_t)(t * 2 + 1) * C2 + n) * PK1 + k] = l;
        }
        for (int i = idx0; i < 27 * C3 * C2; i += stride) {
            int k = i % C2;
            int n = (i / C2) % C3;
            int t = i / (C2 * C3);
            int kw = t % 3, kh = (t / 3) % 3, kd = t / 9;
            float v = w_reg1[((((size_t)n * C2 + k) * 3 + kd) * 3 + kh) * 3 + kw];
            __nv_bfloat16 h = __float2bfloat16(v);
            __nv_bfloat16 l = __float2bfloat16(v - __bfloat162float(h));
            g_wB2[((size_t)(t * 2 + 0) * C3 + n) * PK2 + k] = h;
            g_wB2[((size_t)(t * 2 + 1) * C3 + n) * PK2 + k] = l;
        }
        return;
    }

    __shared__ float ws[27 * 32];
    for (int i = tid; i < 864; i += 256) {
        int k = i >> 5, oc = i & 31;
        ws[i] = w[oc * 27 + k];
    }
    __syncthreads();

    const float* cam = (zi == 0) ? c0 : (zi == 1) ? c1 : (zi == 2) ? c2 : c3;
    int ow = blockIdx.x * 16 + threadIdx.x;
    int oh = blockIdx.y * 16 + threadIdx.y;

    float v[27];
#pragma unroll
    for (int ic = 0; ic < 3; ic++)
#pragma unroll
        for (int kh = 0; kh < 3; kh++)
#pragma unroll
            for (int kw = 0; kw < 3; kw++) {
                int iy = 2 * oh + kh - 1;
                int ix = 2 * ow + kw - 1;
                float t = 0.f;
                if (iy >= 0 && iy < IH && ix >= 0 && ix < IW)
                    t = cam[(size_t)ic * IH * IW + (size_t)iy * IW + ix];
                v[ic * 9 + kh * 3 + kw] = t;
            }

    float4 acc[8];
#pragma unroll
    for (int q = 0; q < 8; q++) acc[q] = make_float4(0.f, 0.f, 0.f, 0.f);
    const float4* ws4 = (const float4*)ws;
#pragma unroll
    for (int k = 0; k < 27; k++) {
        float vv = v[k];
#pragma unroll
        for (int q = 0; q < 8; q++) {
            float4 wv = ws4[k * 8 + q];
            acc[q].x += vv * wv.x;  acc[q].y += vv * wv.y;
            acc[q].z += vv * wv.z;  acc[q].w += vv * wv.w;
        }
    }
    float4* o = (float4*)(g_feat + ((size_t)zi * FH * FW + (size_t)oh * FW + ow) * C1);
#pragma unroll
    for (int q = 0; q < 8; q++) {
        float4 r = acc[q];
        r.x = fmaxf(r.x, 0.f); r.y = fmaxf(r.y, 0.f);
        r.z = fmaxf(r.z, 0.f); r.w = fmaxf(r.w, 0.f);
        o[q] = r;
    }
}

// ---------------- K2: grid_sample, warp-cooperative, 2 d-slices per thread ----------------
__global__ void __launch_bounds__(256)
k_warp(const float* __restrict__ grids)
{
    int tid = threadIdx.x;
    int c   = tid & 7;
    int pid = tid >> 3;
    int pos = blockIdx.x * 32 + pid;
    int d0  = blockIdx.y;
    int cam = blockIdx.z;
    int y = pos / FW, x = pos % FW;

    const float* fb = g_feat + (size_t)cam * FH * FW * C1 + c * 4;

#pragma unroll
    for (int s = 0; s < 2; s++) {
        int d = d0 + s * 2;
        const float* g = grids + ((((size_t)cam * DSLICE + d) * FH + y) * FW + x) * 2;
        float fx = (g[0] + 1.f) * (FW * 0.5f) - 0.5f;
        float fy = (g[1] + 1.f) * (FH * 0.5f) - 0.5f;
        float x0f = floorf(fx), y0f = floorf(fy);
        float wx = fx - x0f,   wy = fy - y0f;
        int x0 = (int)x0f, y0 = (int)y0f;
        int x1 = x0 + 1,   y1 = y0 + 1;
        float vx0 = (x0 >= 0 && x0 < FW) ? 1.f : 0.f;
        float vx1 = (x1 >= 0 && x1 < FW) ? 1.f : 0.f;
        float vy0 = (y0 >= 0 && y0 < FH) ? 1.f : 0.f;
        float vy1 = (y1 >= 0 && y1 < FH) ? 1.f : 0.f;
        float w00 = (1.f - wx) * (1.f - wy) * vx0 * vy0;
        float w01 = wx * (1.f - wy) * vx1 * vy0;
        float w10 = (1.f - wx) * wy * vx0 * vy1;
        float w11 = wx * wy * vx1 * vy1;
        int x0c = min(max(x0, 0), FW - 1), x1c = min(max(x1, 0), FW - 1);
        int y0c = min(max(y0, 0), FH - 1), y1c = min(max(y1, 0), FH - 1);

        float4 a = *(const float4*)(fb + ((size_t)y0c * FW + x0c) * C1);
        float4 b = *(const float4*)(fb + ((size_t)y0c * FW + x1c) * C1);
        float4 e = *(const float4*)(fb + ((size_t)y1c * FW + x0c) * C1);
        float4 f = *(const float4*)(fb + ((size_t)y1c * FW + x1c) * C1);

        float4 r;
        r.x = w00 * a.x + w01 * b.x + w10 * e.x + w11 * f.x;
        r.y = w00 * a.y + w01 * b.y + w10 * e.y + w11 * f.y;
        r.z = w00 * a.z + w01 * b.z + w10 * e.z + w11 * f.z;
        r.w = w00 * a.w + w01 * b.w + w10 * e.w + w11 * f.w;
        *(float4*)(g_warp + ((size_t)(cam * DSLICE + d) * FH * FW + pos) * C1 + c * 4) = r;
    }
}

// ---------------- K3: antialiased resize, warp-cooperative, bf16 hi/lo output ----------------
__global__ void __launch_bounds__(256)
k_resize()
{
    int tid  = threadIdx.x;
    int c    = tid & 7;
    int pid  = tid >> 3;
    int opos = blockIdx.x * 32 + pid;
    int ho   = opos >> 8;
    int wo   = opos & 255;
    int d    = blockIdx.y;
    int cam  = blockIdx.z;

    float sy = (ho + 0.5f) * 1.25f - 0.5f;
    int jy0 = max((int)ceilf(sy - 1.25f), 0);
    int jy1 = min((int)floorf(sy + 1.25f), FH - 1);
    float wyv[4]; int ny = jy1 - jy0 + 1;
    float sumy = 0.f;
    for (int i = 0; i < ny; i++) {
        float w = fmaxf(1.f - fabsf(sy - (float)(jy0 + i)) * 0.8f, 0.f);
        wyv[i] = w; sumy += w;
    }
    for (int i = 0; i < ny; i++) wyv[i] /= sumy;

    float sx = (wo + 0.5f) * 2.5f - 0.5f;
    int jx0 = max((int)ceilf(sx - 2.5f), 0);
    int jx1 = min((int)floorf(sx + 2.5f), FW - 1);
    float wxv[6]; int nx = jx1 - jx0 + 1;
    float sumx = 0.f;
    for (int i = 0; i < nx; i++) {
        float w = fmaxf(1.f - fabsf(sx - (float)(jx0 + i)) * 0.4f, 0.f);
        wxv[i] = w; sumx += w;
    }
    for (int i = 0; i < nx; i++) wxv[i] /= sumx;

    float4 acc = make_float4(0.f, 0.f, 0.f, 0.f);
    const float* base = g_warp + (size_t)(cam * DSLICE + d) * FH * FW * C1 + c * 4;
    for (int iy = 0; iy < ny; iy++) {
        const float* rowb = base + (size_t)(jy0 + iy) * FW * C1;
        for (int ix = 0; ix < nx; ix++) {
            float wgt = wyv[iy] * wxv[ix];
            float4 t = *(const float4*)(rowb + (size_t)(jx0 + ix) * C1);
            acc.x += wgt * t.x; acc.y += wgt * t.y;
            acc.z += wgt * t.z; acc.w += wgt * t.w;
        }
    }
    size_t obase = (((size_t)d * HO + ho) * WO + wo) * CF + cam * C1 + c * 4;
    uint32_t h0, l0, h1, l1;
    split2(acc.x, acc.y, h0, l0);
    split2(acc.z, acc.w, h1, l1);
    *(uint2*)(g_costs_h + obase) = make_uint2(h0, h1);
    *(uint2*)(g_costs_l + obase) = make_uint2(l0, l1);
}

// ---------------- K4: conv3d 3x3x3 pad1 + relu, mma.sync bf16 split, phase-pipelined --------
// 128 threads / 4 warps, single-buffered smem (2 CTAs/SM). Item compute split into 3 phases
// (ah·bh, al·bh, ah·bl); next item's staging issued in 2 cp.async groups at operand-death
// points so B.hi/A.lo transfer hides under phase 3, B.lo under phases 1-2 of the next item.
// conv1: MI=4, NWN=2 (warp M64xN32). conv2: MI=2, NWN=1 (warp M32xN32).
template<int CIN, int COUT, int MI, int NWN, bool OBF>
__global__ void __launch_bounds__(128)
k_conv3d_mma(const __nv_bfloat16* __restrict__ in_h, const __nv_bfloat16* __restrict__ in_l,
             const __nv_bfloat16* __restrict__ wB,
             __nv_bfloat16* __restrict__ out_h, __nv_bfloat16* __restrict__ out_l,
             float* __restrict__ out_f)
{
    constexpr int NT   = 128;
    constexpr int PK   = CIN + 8;
    constexpr int PKB  = PK * 2;             // bytes per smem row
    constexpr int SA   = 130 * PKB;          // one A plane (hi or lo)
    constexpr int BH   = COUT * PKB;         // one B half (hi or lo)
    constexpr int NJ   = (COUT / NWN) / 8;   // 4
    constexpr int KST  = CIN / 16;           // k-steps per item
    constexpr int CH   = CIN / 8;            // 16B chunks per A row per plane

    extern __shared__ char dsm[];
    const uint32_t sBase = smem_u32(dsm);
    const uint32_t sA = sBase;               // [A.hi | A.lo | B.hi | B.lo]
    const uint32_t sB = sBase + 2 * SA;

    int tid  = threadIdx.x;
    int wid  = tid >> 5, lane = tid & 31;
    int gid  = lane >> 2, tig = lane & 3;
    int wM   = wid / NWN;
    int wN   = wid % NWN;
    int ow0  = blockIdx.x * 128;
    int oh   = blockIdx.y, od = blockIdx.z;

    // ---- build valid (kd,kh) list ----
    int zdv[9], zhv[9], t9v[9];
    int nv = 0;
    for (int kd = 0; kd < 3; kd++) {
        int zd = od + kd - 1;
        if (zd < 0 || zd >= DSLICE) continue;
        for (int kh = 0; kh < 3; kh++) {
            int zh = oh + kh - 1;
            if (zh < 0 || zh >= HO) continue;
            zdv[nv] = zd; zhv[nv] = zh; t9v[nv] = kd * 3 + kh;
            nv++;
        }
    }
    int nitems = nv * 3;

    float acc[MI][NJ][4];
#pragma unroll
    for (int mi = 0; mi < MI; mi++)
#pragma unroll
        for (int nj = 0; nj < NJ; nj++)
#pragma unroll
            for (int cc = 0; cc < 4; cc++) acc[mi][nj][cc] = 0.f;

    // stage one A plane (pl: 0=hi, 1=lo) for (kd,kh) group ai
    auto stage_A_pl = [&](int ai, int pl) {
        size_t inoff = ((size_t)zdv[ai] * HO + zhv[ai]) * WO * CIN;
        const __nv_bfloat16* src = pl ? in_l : in_h;
        uint32_t dA = sA + (uint32_t)pl * SA;
        for (int i = tid; i < 130 * CH; i += NT) {
            int r = i / CH, g = i % CH;
            int p = ow0 - 1 + r;
            bool v = (p >= 0 && p < WO);
            int pc = v ? p : 0;
            cp_async16(dA + (uint32_t)r * PKB + g * 16,
                       src + inoff + (size_t)pc * CIN + g * 8, v);
        }
    };
    // stage one B half (0=hi, 1=lo) for item j
    auto stage_B_half = [&](int j, int half) {
        int t = t9v[j / 3] * 3 + (j % 3);
        const char* src = (const char*)(wB + ((size_t)t * 2 + half) * COUT * PK);
        uint32_t dB = sB + (uint32_t)half * BH;
        for (int i = tid; i < BH / 16; i += NT)
            cp_async16(dB + i * 16, src + i * 16, true);
    };
    // one split-term phase: 0 = ah*bh, 1 = al*bh, 2 = ah*bl
    auto do_phase = [&](int term, uint32_t aB0, uint32_t bB0) {
        uint32_t aoff = (term == 1) ? (uint32_t)SA : 0u;
        uint32_t boff = (term == 2) ? (uint32_t)BH : 0u;
#pragma unroll
        for (int ks = 0; ks < KST; ks++) {
            uint32_t ko = (uint32_t)ks * 32;
            uint32_t av[MI][4], bv[NJ][2];
#pragma unroll
            for (int mi = 0; mi < MI; mi++) {
                uint32_t a = aB0 + aoff + mi * 16 * PKB + ko;
                av[mi][0] = lds32(a);
                av[mi][1] = lds32(a + 8 * PKB);
                av[mi][2] = lds32(a + 16);
                av[mi][3] = lds32(a + 8 * PKB + 16);
            }
#pragma unroll
            for (int nj = 0; nj < NJ; nj++) {
                uint32_t bb = bB0 + boff + nj * 8 * PKB + ko;
                bv[nj][0] = lds32(bb);
                bv[nj][1] = lds32(bb + 16);
            }
#pragma unroll
            for (int nj = 0; nj < NJ; nj++)
#pragma unroll
                for (int mi = 0; mi < MI; mi++)
                    mma_bf16(acc[mi][nj][0], acc[mi][nj][1], acc[mi][nj][2], acc[mi][nj][3],
                             av[mi][0], av[mi][1], av[mi][2], av[mi][3],
                             bv[nj][0], bv[nj][1]);
        }
    };

    // prologue: stage item 0 fully (one group)
    stage_A_pl(0, 0);
    stage_A_pl(0, 1);
    stage_B_half(0, 0);
    stage_B_half(0, 1);
    cp_commit();

    for (int j = 0; j < nitems; j++) {
        int jn = j + 1;
        bool rn = (jn < nitems) && ((jn % 3) == 0);

        // top-of-item wait: restage items need G2 (A.hi) too
        if ((j % 3) == 0) cp_wait0(); else cp_wait1();
        __syncthreads();

        int q = j % 3;
        uint32_t aB0 = sA + (uint32_t)(q + wM * (MI * 16) + gid) * PKB + tig * 4;
        uint32_t bB0 = sB + (uint32_t)(wN * 32 + gid) * PKB + tig * 4;

        do_phase(0, aB0, bB0);           // ah*bh   (B.lo(j) may still be arriving)
        do_phase(1, aB0, bB0);           // al*bh
        __syncthreads();                 // B.hi(j), A.lo(j) dead block-wide
        if (jn < nitems) {
            stage_B_half(jn, 0);         // G1(jn): B.hi
            if (rn) stage_A_pl(jn / 3, 1);   //        + A.lo
            cp_commit();
        }
        if (jn < nitems) cp_wait1(); else cp_wait0();   // retire B.lo(j)'s group
        __syncthreads();
        do_phase(2, aB0, bB0);           // ah*bl — overlaps G1(jn) transfer
        __syncthreads();                 // B.lo(j) dead; A planes dead if restaging
        if (jn < nitems) {
            stage_B_half(jn, 1);         // G2(jn): B.lo
            if (rn) stage_A_pl(jn / 3, 0);   //        + A.hi
            cp_commit();
        }
    }

    // ---- epilogue: relu + store ----
#pragma unroll
    for (int mi = 0; mi < MI; mi++) {
        int row = wM * (MI * 16) + mi * 16 + gid;
        size_t base0 = (((size_t)od * HO + oh) * WO + ow0 + row) * COUT;
        size_t base1 = base0 + 8 * COUT;      // row + 8
#pragma unroll
        for (int nj = 0; nj < NJ; nj++) {
            int col = wN * 32 + nj * 8 + tig * 2;
            float v00 = fmaxf(acc[mi][nj][0], 0.f);
            float v01 = fmaxf(acc[mi][nj][1], 0.f);
            float v10 = fmaxf(acc[mi][nj][2], 0.f);
            float v11 = fmaxf(acc[mi][nj][3], 0.f);
            if (OBF) {
                uint32_t h0, l0, h1, l1;
                split2(v00, v01, h0, l0);
                split2(v10, v11, h1, l1);
                *(uint32_t*)(out_h + base0 + col) = h0;
                *(uint32_t*)(out_l + base0 + col) = l0;
                *(uint32_t*)(out_h + base1 + col) = h1;
                *(uint32_t*)(out_l + base1 + col) = l1;
            } else {
                *(float2*)(out_f + base0 + col) = make_float2(v00, v01);
                *(float2*)(out_f + base1 + col) = make_float2(v10, v11);
            }
        }
    }
}

// ---------------- K5: conv3d 32->1 (no relu), smem-tiled ----------------
__global__ void __launch_bounds__(256)
k_reg2(const float* __restrict__ w2)
{
    __shared__ float ws_t[27 * 32];                 // [k27][ic32]
    __shared__ float tile[10][34][32];              // [zh][zw][c]
    int tx = threadIdx.x & 31;
    int ty = threadIdx.x >> 5;
    int tid = threadIdx.x;
    for (int i = tid; i < 864; i += 256) {
        int ic = i / 27, k = i % 27;
        ws_t[k * 32 + ic] = w2[i];
    }

    int ow0 = blockIdx.x * 32;
    int oh0 = blockIdx.y * 8;
    int od  = blockIdx.z;
    int ow = ow0 + tx, oh = oh0 + ty;

    float acc = 0.f;
    for (int kd = 0; kd < 3; kd++) {
        int zd = od + kd - 1;
        if (zd < 0 || zd >= DSLICE) continue;
        __syncthreads();
        for (int i = tid; i < 10 * 34 * 8; i += 256) {
            int g  = i & 7;
            int zw = (i >> 3) % 34 + ow0 - 1;
            int zh = (i >> 3) / 34 + oh0 - 1;
            bool v = (zw >= 0 && zw < WO && zh >= 0 && zh < HO);
            int zwc = v ? zw : 0, zhc = v ? zh : 0;
            const float* src = g_x2 + (((size_t)zd * HO + zhc) * WO + zwc) * C3 + g * 4;
            cp_async16(smem_u32(&tile[(i >> 3) / 34][(i >> 3) % 34][g * 4]), src, v);
        }
        cp_commit();
        cp_wait0();
        __syncthreads();

#pragma unroll
        for (int kh = 0; kh < 3; kh++) {
#pragma unroll
            for (int kw = 0; kw < 3; kw++) {
                int k = kd * 9 + kh * 3 + kw;
                const float4* p  = (const float4*)&tile[ty + kh][tx + kw][0];
                const float4* wv = (const float4*)&ws_t[k * 32];
#pragma unroll
                for (int qq = 0; qq < 8; qq++) {
                    float4 a = p[qq], b = wv[qq];
                    acc += a.x * b.x + a.y * b.y + a.z * b.z + a.w * b.w;
                }
            }
        }
    }
    g_x3[((size_t)od * HO + oh) * WO + ow] = acc;
}

// ---------------- K6: D-resize 4->8 + softmax + expectation ----------------
__global__ void k_final(float* __restrict__ outp)
{
    int pos = blockIdx.x * 256 + threadIdx.x;
    float v[4];
#pragma unroll
    for (int d = 0; d < 4; d++) v[d] = g_x3[(size_t)d * (HO * WO) + pos];

    float y[8];
#pragma unroll
    for (int o = 0; o < 8; o++) {
        float s = 0.5f * o - 0.25f;
        int j0 = max(0, (int)ceilf(s - 1.f));
        int j1 = min(3, (int)floorf(s + 1.f));
        float acc = 0.f, wsum = 0.f;
        for (int j = j0; j <= j1; j++) {
            float w = fmaxf(1.f - fabsf(s - (float)j), 0.f);
            acc += w * v[j]; wsum += w;
        }
        y[o] = acc / wsum;
    }
    float m = y[0];
#pragma unroll
    for (int o = 1; o < 8; o++) m = fmaxf(m, y[o]);
    float esum = 0.f, dsum = 0.f;
#pragma unroll
    for (int o = 0; o < 8; o++) {
        float e = expf(y[o] - m);
        esum += e;
        dsum += e * (float)o;
    }
    outp[pos] = dsum / esum;
}

// ---------------- host launch ----------------
extern "C" void kernel_launch(void* const* d_in, const int* in_sizes, int n_in,
                              void* d_out, int out_size)
{
    const float* cams[4] = { (const float*)d_in[0], (const float*)d_in[1],
                             (const float*)d_in[2], (const float*)d_in[3] };
    const float* grids    = (const float*)d_in[4];
    const float* w_feat   = (const float*)d_in[5];
    const float* w_fusion = (const float*)d_in[6];
    const float* w_reg1   = (const float*)d_in[7];
    const float* w_reg2   = (const float*)d_in[8];
    float* out = (float*)d_out;

    __nv_bfloat16 *p_wB1, *p_wB2, *p_ch, *p_cl, *p_x1h, *p_x1l;
    float* p_x2;
    cudaGetSymbolAddress((void**)&p_x2,  g_x2);
    cudaGetSymbolAddress((void**)&p_wB1, g_wB1);
    cudaGetSymbolAddress((void**)&p_wB2, g_wB2);
    cudaGetSymbolAddress((void**)&p_ch,  g_costs_h);
    cudaGetSymbolAddress((void**)&p_cl,  g_costs_l);
    cudaGetSymbolAddress((void**)&p_x1h, g_x1_h);
    cudaGetSymbolAddress((void**)&p_x1l, g_x1_l);

    // single-buffered: A(hi+lo) + B(hi+lo) -> 2 CTAs/SM
    const int SMEM1 = 2 * (130 * PK1 * 2) + 2 * C2 * PK1 * 2;   // 105536
    const int SMEM2 = 2 * (130 * PK2 * 2) + 2 * C3 * PK2 * 2;   //  46656
    cudaFuncSetAttribute((const void*)k_conv3d_mma<CF, C2, 4, 2, true>,
                         cudaFuncAttributeMaxDynamicSharedMemorySize, SMEM1);
    cudaFuncSetAttribute((const void*)k_conv3d_mma<C2, C3, 2, 1, false>,
                         cudaFuncAttributeMaxDynamicSharedMemorySize, SMEM2);

    // 1: feature extraction + weight prep (fused)
    k_feat4w<<<dim3(FW / 16, FH / 16, 5), dim3(16, 16)>>>(
        cams[0], cams[1], cams[2], cams[3], w_feat, w_fusion, w_reg1);

    // 2: plane sweep warp (2 d per thread)
    k_warp<<<dim3(FH * FW / 32, 2, CAMS), 256>>>(grids);

    // 3: antialiased resize -> bf16 hi/lo cost volume
    k_resize<<<dim3(HO * WO / 32, DSLICE, CAMS), 256>>>();

    // 4: conv1 (profiled launch)  5: conv2 — phase-pipelined staging, 2 CTAs/SM
    k_conv3d_mma<CF, C2, 4, 2, true ><<<dim3(WO / 128, HO, DSLICE), 128, SMEM1>>>(p_ch,  p_cl,  p_wB1, p_x1h, p_x1l, nullptr);
    k_conv3d_mma<C2, C3, 2, 1, false><<<dim3(WO / 128, HO, DSLICE), 128, SMEM2>>>(p_x1h, p_x1l, p_wB2, nullptr, nullptr, p_x2);

    // 6: squeeze conv
    k_reg2<<<dim3(WO / 32, HO / 8, DSLICE), 256>>>(w_reg2);

    // 7: disparity regression
    k_final<<<(HO * WO) / 256, 256>>>(out);
}

// round 13
// speedup vs baseline: 2.5096x; 1.6118x over previous
#include <cuda_runtime.h>
#include <cuda_fp16.h>
#include <cstdint>
#include <math.h>

// ---------------- problem constants ----------------
#define CAMS   4
#define DSLICE 4      // D = NDISP/2
#define NDISP  8
#define IH     640
#define IW     1280
#define FH     320
#define FW     640
#define C1     32
#define HO     256
#define WO     256
#define CF     128    // fused cost channels
#define C2     64
#define C3     32

#define PK1    (CF + 8)    // padded K (elements) conv1
#define PK2    (C2 + 8)    // padded K conv2

// ---------------- scratch (static device memory; no allocs) ----------------
__device__ float g_feat [(size_t)CAMS*FH*FW*C1];              // [cam][y][x][c]
__device__ float g_warp [(size_t)CAMS*DSLICE*FH*FW*C1];       // [cam][d][y][x][c]
__device__ __half g_costs[(size_t)DSLICE*HO*WO*CF];           // fp16 cost volume [d][h][w][c]
__device__ __half g_x1   [(size_t)DSLICE*HO*WO*C2];           // fp16
__device__ float  g_x2   [(size_t)DSLICE*HO*WO*C3];
__device__ float  g_x3   [(size_t)DSLICE*HO*WO];
__device__ __half g_wB1  [27*C2*PK1];   // conv1 weights fp16 [tap][n][PK1]
__device__ __half g_wB2  [27*C3*PK2];   // conv2 weights fp16 [tap][n][PK2]

// =====================================================================
// helpers
// =====================================================================
__device__ __forceinline__ uint32_t smem_u32(const void* p) {
    uint32_t a;
    asm("{ .reg .u64 t; cvta.to.shared.u64 t, %1; cvt.u32.u64 %0, t; }" : "=r"(a) : "l"(p));
    return a;
}
__device__ __forceinline__ uint32_t lds32(uint32_t addr) {
    uint32_t r;
    asm volatile("ld.shared.b32 %0, [%1];" : "=r"(r) : "r"(addr));
    return r;
}
__device__ __forceinline__ void cp_async16(uint32_t dst, const void* src, bool valid) {
    int sz = valid ? 16 : 0;
    asm volatile("cp.async.cg.shared.global [%0], [%1], 16, %2;"
                 :: "r"(dst), "l"(src), "r"(sz) : "memory");
}
__device__ __forceinline__ void cp_commit() {
    asm volatile("cp.async.commit_group;" ::: "memory");
}
__device__ __forceinline__ void cp_wait0() {
    asm volatile("cp.async.wait_group 0;" ::: "memory");
}
__device__ __forceinline__ void mma_f16(float& d0, float& d1, float& d2, float& d3,
                                        uint32_t a0, uint32_t a1, uint32_t a2, uint32_t a3,
                                        uint32_t b0, uint32_t b1)
{
    asm volatile(
        "mma.sync.aligned.m16n8k16.row.col.f32.f16.f16.f32 "
        "{%0,%1,%2,%3}, {%4,%5,%6,%7}, {%8,%9}, {%0,%1,%2,%3};"
        : "+f"(d0), "+f"(d1), "+f"(d2), "+f"(d3)
        : "r"(a0), "r"(a1), "r"(a2), "r"(a3), "r"(b0), "r"(b1));
}

// ---------------- K1: conv2d 3->32 s2 + relu (grid.z<4) fused with weight prep (grid.z==4) ----
__global__ void k_feat4w(const float* __restrict__ c0, const float* __restrict__ c1,
                         const float* __restrict__ c2, const float* __restrict__ c3,
                         const float* __restrict__ w,
                         const float* __restrict__ w_fusion, const float* __restrict__ w_reg1)
{
    int tid = threadIdx.y * 16 + threadIdx.x;
    int zi  = blockIdx.z;

    if (zi == 4) {
        int idx0   = (blockIdx.y * (FW / 16) + blockIdx.x) * 256 + tid;
        int stride = (FW / 16) * (FH / 16) * 256;
        for (int i = idx0; i < 27 * C2 * CF; i += stride) {
            int k = i % CF;
            int n = (i / CF) % C2;
            int t = i / (CF * C2);
            int kw = t % 3, kh = (t / 3) % 3, kd = t / 9;
            float v = w_fusion[((((size_t)n * CF + k) * 3 + kd) * 3 + kh) * 3 + kw];
            g_wB1[((size_t)t * C2 + n) * PK1 + k] = __float2half(v);
        }
        for (int i = idx0; i < 27 * C3 * C2; i += stride) {
            int k = i % C2;
            int n = (i / C2) % C3;
            int t = i / (C2 * C3);
            int kw = t % 3, kh = (t / 3) % 3, kd = t / 9;
            float v = w_reg1[((((size_t)n * C2 + k) * 3 + kd) * 3 + kh) * 3 + kw];
            g_wB2[((size_t)t * C3 + n) * PK2 + k] = __float2half(v);
        }
        return;
    }

    __shared__ float ws[27 * 32];
    for (int i = tid; i < 864; i += 256) {
        int k = i >> 5, oc = i & 31;
        ws[i] = w[oc * 27 + k];
    }
    __syncthreads();

    const float* cam = (zi == 0) ? c0 : (zi == 1) ? c1 : (zi == 2) ? c2 : c3;
    int ow = blockIdx.x * 16 + threadIdx.x;
    int oh = blockIdx.y * 16 + threadIdx.y;

    float v[27];
#pragma unroll
    for (int ic = 0; ic < 3; ic++)
#pragma unroll
        for (int kh = 0; kh < 3; kh++)
#pragma unroll
            for (int kw = 0; kw < 3; kw++) {
                int iy = 2 * oh + kh - 1;
                int ix = 2 * ow + kw - 1;
                float t = 0.f;
                if (iy >= 0 && iy < IH && ix >= 0 && ix < IW)
                    t = cam[(size_t)ic * IH * IW + (size_t)iy * IW + ix];
                v[ic * 9 + kh * 3 + kw] = t;
            }

    float4 acc[8];
#pragma unroll
    for (int q = 0; q < 8; q++) acc[q] = make_float4(0.f, 0.f, 0.f, 0.f);
    const float4* ws4 = (const float4*)ws;
#pragma unroll
    for (int k = 0; k < 27; k++) {
        float vv = v[k];
#pragma unroll
        for (int q = 0; q < 8; q++) {
            float4 wv = ws4[k * 8 + q];
            acc[q].x += vv * wv.x;  acc[q].y += vv * wv.y;
            acc[q].z += vv * wv.z;  acc[q].w += vv * wv.w;
        }
    }
    float4* o = (float4*)(g_feat + ((size_t)zi * FH * FW + (size_t)oh * FW + ow) * C1);
#pragma unroll
    for (int q = 0; q < 8; q++) {
        float4 r = acc[q];
        r.x = fmaxf(r.x, 0.f); r.y = fmaxf(r.y, 0.f);
        r.z = fmaxf(r.z, 0.f); r.w = fmaxf(r.w, 0.f);
        o[q] = r;
    }
}

// ---------------- K2: grid_sample, warp-cooperative, 2 d-slices per thread ----------------
__global__ void __launch_bounds__(256)
k_warp(const float* __restrict__ grids)
{
    int tid = threadIdx.x;
    int c   = tid & 7;
    int pid = tid >> 3;
    int pos = blockIdx.x * 32 + pid;
    int d0  = blockIdx.y;
    int cam = blockIdx.z;
    int y = pos / FW, x = pos % FW;

    const float* fb = g_feat + (size_t)cam * FH * FW * C1 + c * 4;

#pragma unroll
    for (int s = 0; s < 2; s++) {
        int d = d0 + s * 2;
        const float* g = grids + ((((size_t)cam * DSLICE + d) * FH + y) * FW + x) * 2;
        float fx = (g[0] + 1.f) * (FW * 0.5f) - 0.5f;
        float fy = (g[1] + 1.f) * (FH * 0.5f) - 0.5f;
        float x0f = floorf(fx), y0f = floorf(fy);
        float wx = fx - x0f,   wy = fy - y0f;
        int x0 = (int)x0f, y0 = (int)y0f;
        int x1 = x0 + 1,   y1 = y0 + 1;
        float vx0 = (x0 >= 0 && x0 < FW) ? 1.f : 0.f;
        float vx1 = (x1 >= 0 && x1 < FW) ? 1.f : 0.f;
        float vy0 = (y0 >= 0 && y0 < FH) ? 1.f : 0.f;
        float vy1 = (y1 >= 0 && y1 < FH) ? 1.f : 0.f;
        float w00 = (1.f - wx) * (1.f - wy) * vx0 * vy0;
        float w01 = wx * (1.f - wy) * vx1 * vy0;
        float w10 = (1.f - wx) * wy * vx0 * vy1;
        float w11 = wx * wy * vx1 * vy1;
        int x0c = min(max(x0, 0), FW - 1), x1c = min(max(x1, 0), FW - 1);
        int y0c = min(max(y0, 0), FH - 1), y1c = min(max(y1, 0), FH - 1);

        float4 a = *(const float4*)(fb + ((size_t)y0c * FW + x0c) * C1);
        float4 b = *(const float4*)(fb + ((size_t)y0c * FW + x1c) * C1);
        float4 e = *(const float4*)(fb + ((size_t)y1c * FW + x0c) * C1);
        float4 f = *(const float4*)(fb + ((size_t)y1c * FW + x1c) * C1);

        float4 r;
        r.x = w00 * a.x + w01 * b.x + w10 * e.x + w11 * f.x;
        r.y = w00 * a.y + w01 * b.y + w10 * e.y + w11 * f.y;
        r.z = w00 * a.z + w01 * b.z + w10 * e.z + w11 * f.z;
        r.w = w00 * a.w + w01 * b.w + w10 * e.w + w11 * f.w;
        *(float4*)(g_warp + ((size_t)(cam * DSLICE + d) * FH * FW + pos) * C1 + c * 4) = r;
    }
}

// ---------------- K3: antialiased resize, warp-cooperative, fp16 output ----------------
__global__ void __launch_bounds__(256)
k_resize()
{
    int tid  = threadIdx.x;
    int c    = tid & 7;
    int pid  = tid >> 3;
    int opos = blockIdx.x * 32 + pid;
    int ho   = opos >> 8;
    int wo   = opos & 255;
    int d    = blockIdx.y;
    int cam  = blockIdx.z;

    float sy = (ho + 0.5f) * 1.25f - 0.5f;
    int jy0 = max((int)ceilf(sy - 1.25f), 0);
    int jy1 = min((int)floorf(sy + 1.25f), FH - 1);
    float wyv[4]; int ny = jy1 - jy0 + 1;
    float sumy = 0.f;
    for (int i = 0; i < ny; i++) {
        float w = fmaxf(1.f - fabsf(sy - (float)(jy0 + i)) * 0.8f, 0.f);
        wyv[i] = w; sumy += w;
    }
    for (int i = 0; i < ny; i++) wyv[i] /= sumy;

    float sx = (wo + 0.5f) * 2.5f - 0.5f;
    int jx0 = max((int)ceilf(sx - 2.5f), 0);
    int jx1 = min((int)floorf(sx + 2.5f), FW - 1);
    float wxv[6]; int nx = jx1 - jx0 + 1;
    float sumx = 0.f;
    for (int i = 0; i < nx; i++) {
        float w = fmaxf(1.f - fabsf(sx - (float)(jx0 + i)) * 0.4f, 0.f);
        wxv[i] = w; sumx += w;
    }
    for (int i = 0; i < nx; i++) wxv[i] /= sumx;

    float4 acc = make_float4(0.f, 0.f, 0.f, 0.f);
    const float* base = g_warp + (size_t)(cam * DSLICE + d) * FH * FW * C1 + c * 4;
    for (int iy = 0; iy < ny; iy++) {
        const float* rowb = base + (size_t)(jy0 + iy) * FW * C1;
        for (int ix = 0; ix < nx; ix++) {
            float wgt = wyv[iy] * wxv[ix];
            float4 t = *(const float4*)(rowb + (size_t)(jx0 + ix) * C1);
            acc.x += wgt * t.x; acc.y += wgt * t.y;
            acc.z += wgt * t.z; acc.w += wgt * t.w;
        }
    }
    size_t obase = (((size_t)d * HO + ho) * WO + wo) * CF + cam * C1 + c * 4;
    __half2 p0 = __floats2half2_rn(acc.x, acc.y);
    __half2 p1 = __floats2half2_rn(acc.z, acc.w);
    *(uint2*)(g_costs + obase) = make_uint2(*(uint32_t*)&p0, *(uint32_t*)&p1);
}

// ---------------- K4: conv3d 3x3x3 pad1 + relu, single-term fp16 mma.sync -------------------
// 128 threads / 4 warps, single A plane + single B tap (fp16) -> 52.8/23.3 KB smem -> 4 CTAs/SM.
// conv1: MI=4, NWN=2 (warp M64xN32). conv2: MI=2, NWN=1 (warp M32xN32).
template<int CIN, int COUT, int MI, int NWN, bool OBF>
__global__ void __launch_bounds__(128)
k_conv3d_mma(const __half* __restrict__ in, const __half* __restrict__ wB,
             __half* __restrict__ out_hlf, float* __restrict__ out_f)
{
    constexpr int NT   = 128;
    constexpr int PK   = CIN + 8;
    constexpr int PKB  = PK * 2;             // bytes per smem row
    constexpr int SA   = 130 * PKB;          // A plane bytes
    constexpr int TB   = COUT * PKB;         // B tap bytes
    constexpr int NJ   = (COUT / NWN) / 8;   // 4
    constexpr int KST  = CIN / 16;           // k-steps per item
    constexpr int CH   = CIN / 8;            // 16B chunks per A row

    extern __shared__ char dsm[];
    const uint32_t sBase = smem_u32(dsm);
    const uint32_t sA = sBase;               // [A | B]
    const uint32_t sB = sBase + SA;

    int tid  = threadIdx.x;
    int wid  = tid >> 5, lane = tid & 31;
    int gid  = lane >> 2, tig = lane & 3;
    int wM   = wid / NWN;
    int wN   = wid % NWN;
    int ow0  = blockIdx.x * 128;
    int oh   = blockIdx.y, od = blockIdx.z;

    // ---- build valid (kd,kh) list ----
    int zdv[9], zhv[9], t9v[9];
    int nv = 0;
    for (int kd = 0; kd < 3; kd++) {
        int zd = od + kd - 1;
        if (zd < 0 || zd >= DSLICE) continue;
        for (int kh = 0; kh < 3; kh++) {
            int zh = oh + kh - 1;
            if (zh < 0 || zh >= HO) continue;
            zdv[nv] = zd; zhv[nv] = zh; t9v[nv] = kd * 3 + kh;
            nv++;
        }
    }
    int nitems = nv * 3;

    float acc[MI][NJ][4];
#pragma unroll
    for (int mi = 0; mi < MI; mi++)
#pragma unroll
        for (int nj = 0; nj < NJ; nj++)
#pragma unroll
            for (int cc = 0; cc < 4; cc++) acc[mi][nj][cc] = 0.f;

    auto stage_A = [&](int ai) {
        size_t inoff = ((size_t)zdv[ai] * HO + zhv[ai]) * WO * CIN;
        for (int i = tid; i < 130 * CH; i += NT) {
            int r = i / CH, g = i % CH;
            int p = ow0 - 1 + r;
            bool v = (p >= 0 && p < WO);
            int pc = v ? p : 0;
            cp_async16(sA + (uint32_t)r * PKB + g * 16,
                       in + inoff + (size_t)pc * CIN + g * 8, v);
        }
    };
    auto stage_B = [&](int j) {
        int t = t9v[j / 3] * 3 + (j % 3);
        const char* src = (const char*)(wB + (size_t)t * COUT * PK);
        for (int i = tid; i < TB / 16; i += NT)
            cp_async16(sB + i * 16, src + i * 16, true);
    };

    for (int j = 0; j < nitems; j++) {
        if (j % 3 == 0) stage_A(j / 3);
        stage_B(j);
        cp_commit();
        cp_wait0();
        __syncthreads();

        int q = j % 3;
        uint32_t aB0 = sA + (uint32_t)(q + wM * (MI * 16) + gid) * PKB + tig * 4;
        uint32_t bB0 = sB + (uint32_t)(wN * 32 + gid) * PKB + tig * 4;
#pragma unroll
        for (int ks = 0; ks < KST; ks++) {
            uint32_t ko = (uint32_t)ks * 32;
            uint32_t av[MI][4], bv[NJ][2];
#pragma unroll
            for (int mi = 0; mi < MI; mi++) {
                uint32_t a = aB0 + mi * 16 * PKB + ko;
                av[mi][0] = lds32(a);
                av[mi][1] = lds32(a + 8 * PKB);
                av[mi][2] = lds32(a + 16);
                av[mi][3] = lds32(a + 8 * PKB + 16);
            }
#pragma unroll
            for (int nj = 0; nj < NJ; nj++) {
                uint32_t bb = bB0 + nj * 8 * PKB + ko;
                bv[nj][0] = lds32(bb);
                bv[nj][1] = lds32(bb + 16);
            }
#pragma unroll
            for (int nj = 0; nj < NJ; nj++)
#pragma unroll
                for (int mi = 0; mi < MI; mi++)
                    mma_f16(acc[mi][nj][0], acc[mi][nj][1], acc[mi][nj][2], acc[mi][nj][3],
                            av[mi][0], av[mi][1], av[mi][2], av[mi][3],
                            bv[nj][0], bv[nj][1]);
        }
        __syncthreads();
    }

    // ---- epilogue: relu + store ----
#pragma unroll
    for (int mi = 0; mi < MI; mi++) {
        int row = wM * (MI * 16) + mi * 16 + gid;
        size_t base0 = (((size_t)od * HO + oh) * WO + ow0 + row) * COUT;
        size_t base1 = base0 + 8 * COUT;      // row + 8
#pragma unroll
        for (int nj = 0; nj < NJ; nj++) {
            int col = wN * 32 + nj * 8 + tig * 2;
            float v00 = fmaxf(acc[mi][nj][0], 0.f);
            float v01 = fmaxf(acc[mi][nj][1], 0.f);
            float v10 = fmaxf(acc[mi][nj][2], 0.f);
            float v11 = fmaxf(acc[mi][nj][3], 0.f);
            if (OBF) {
                __half2 p0 = __floats2half2_rn(v00, v01);
                __half2 p1 = __floats2half2_rn(v10, v11);
                *(uint32_t*)(out_hlf + base0 + col) = *(uint32_t*)&p0;
                *(uint32_t*)(out_hlf + base1 + col) = *(uint32_t*)&p1;
            } else {
                *(float2*)(out_f + base0 + col) = make_float2(v00, v01);
                *(float2*)(out_f + base1 + col) = make_float2(v10, v11);
            }
        }
    }
}

// ---------------- K5: conv3d 32->1 (no relu), smem-tiled ----------------
__global__ void __launch_bounds__(256)
k_reg2(const float* __restrict__ w2)
{
    __shared__ float ws_t[27 * 32];                 // [k27][ic32]
    __shared__ float tile[10][34][32];              // [zh][zw][c]
    int tx = threadIdx.x & 31;
    int ty = threadIdx.x >> 5;
    int tid = threadIdx.x;
    for (int i = tid; i < 864; i += 256) {
        int ic = i / 27, k = i % 27;
        ws_t[k * 32 + ic] = w2[i];
    }

    int ow0 = blockIdx.x * 32;
    int oh0 = blockIdx.y * 8;
    int od  = blockIdx.z;
    int ow = ow0 + tx, oh = oh0 + ty;

    float acc = 0.f;
    for (int kd = 0; kd < 3; kd++) {
        int zd = od + kd - 1;
        if (zd < 0 || zd >= DSLICE) continue;
        __syncthreads();
        for (int i = tid; i < 10 * 34 * 8; i += 256) {
            int g  = i & 7;
            int zw = (i >> 3) % 34 + ow0 - 1;
            int zh = (i >> 3) / 34 + oh0 - 1;
            bool v = (zw >= 0 && zw < WO && zh >= 0 && zh < HO);
            int zwc = v ? zw : 0, zhc = v ? zh : 0;
            const float* src = g_x2 + (((size_t)zd * HO + zhc) * WO + zwc) * C3 + g * 4;
            cp_async16(smem_u32(&tile[(i >> 3) / 34][(i >> 3) % 34][g * 4]), src, v);
        }
        cp_commit();
        cp_wait0();
        __syncthreads();

#pragma unroll
        for (int kh = 0; kh < 3; kh++) {
#pragma unroll
            for (int kw = 0; kw < 3; kw++) {
                int k = kd * 9 + kh * 3 + kw;
                const float4* p  = (const float4*)&tile[ty + kh][tx + kw][0];
                const float4* wv = (const float4*)&ws_t[k * 32];
#pragma unroll
                for (int qq = 0; qq < 8; qq++) {
                    float4 a = p[qq], b = wv[qq];
                    acc += a.x * b.x + a.y * b.y + a.z * b.z + a.w * b.w;
                }
            }
        }
    }
    g_x3[((size_t)od * HO + oh) * WO + ow] = acc;
}

// ---------------- K6: D-resize 4->8 + softmax + expectation ----------------
__global__ void k_final(float* __restrict__ outp)
{
    int pos = blockIdx.x * 256 + threadIdx.x;
    float v[4];
#pragma unroll
    for (int d = 0; d < 4; d++) v[d] = g_x3[(size_t)d * (HO * WO) + pos];

    float y[8];
#pragma unroll
    for (int o = 0; o < 8; o++) {
        float s = 0.5f * o - 0.25f;
        int j0 = max(0, (int)ceilf(s - 1.f));
        int j1 = min(3, (int)floorf(s + 1.f));
        float acc = 0.f, wsum = 0.f;
        for (int j = j0; j <= j1; j++) {
            float w = fmaxf(1.f - fabsf(s - (float)j), 0.f);
            acc += w * v[j]; wsum += w;
        }
        y[o] = acc / wsum;
    }
    float m = y[0];
#pragma unroll
    for (int o = 1; o < 8; o++) m = fmaxf(m, y[o]);
    float esum = 0.f, dsum = 0.f;
#pragma unroll
    for (int o = 0; o < 8; o++) {
        float e = expf(y[o] - m);
        esum += e;
        dsum += e * (float)o;
    }
    outp[pos] = dsum / esum;
}

// ---------------- host launch ----------------
extern "C" void kernel_launch(void* const* d_in, const int* in_sizes, int n_in,
                              void* d_out, int out_size)
{
    const float* cams[4] = { (const float*)d_in[0], (const float*)d_in[1],
                             (const float*)d_in[2], (const float*)d_in[3] };
    const float* grids    = (const float*)d_in[4];
    const float* w_feat   = (const float*)d_in[5];
    const float* w_fusion = (const float*)d_in[6];
    const float* w_reg1   = (const float*)d_in[7];
    const float* w_reg2   = (const float*)d_in[8];
    float* out = (float*)d_out;

    __half *p_wB1, *p_wB2, *p_costs, *p_x1;
    float* p_x2;
    cudaGetSymbolAddress((void**)&p_x2,    g_x2);
    cudaGetSymbolAddress((void**)&p_wB1,   g_wB1);
    cudaGetSymbolAddress((void**)&p_wB2,   g_wB2);
    cudaGetSymbolAddress((void**)&p_costs, g_costs);
    cudaGetSymbolAddress((void**)&p_x1,    g_x1);

    // single fp16 A plane + single fp16 B tap
    const int SMEM1 = 130 * PK1 * 2 + C2 * PK1 * 2;   // 35360 + 17408 = 52768 -> 4 CTAs/SM
    const int SMEM2 = 130 * PK2 * 2 + C3 * PK2 * 2;   // 18720 +  4608 = 23328
    cudaFuncSetAttribute((const void*)k_conv3d_mma<CF, C2, 4, 2, true>,
                         cudaFuncAttributeMaxDynamicSharedMemorySize, SMEM1);
    cudaFuncSetAttribute((const void*)k_conv3d_mma<C2, C3, 2, 1, false>,
                         cudaFuncAttributeMaxDynamicSharedMemorySize, SMEM2);

    // 1: feature extraction + weight prep (fused)
    k_feat4w<<<dim3(FW / 16, FH / 16, 5), dim3(16, 16)>>>(
        cams[0], cams[1], cams[2], cams[3], w_feat, w_fusion, w_reg1);

    // 2: plane sweep warp (2 d per thread)
    k_warp<<<dim3(FH * FW / 32, 2, CAMS), 256>>>(grids);

    // 3: antialiased resize -> fp16 cost volume
    k_resize<<<dim3(HO * WO / 32, DSLICE, CAMS), 256>>>();

    // 4: conv1 (profiled launch)  5: conv2 — single-term fp16, 4 CTAs/SM
    k_conv3d_mma<CF, C2, 4, 2, true ><<<dim3(WO / 128, HO, DSLICE), 128, SMEM1>>>(p_costs, p_wB1, p_x1, nullptr);
    k_conv3d_mma<C2, C3, 2, 1, false><<<dim3(WO / 128, HO, DSLICE), 128, SMEM2>>>(p_x1, p_wB2, nullptr, p_x2);

    // 6: squeeze conv
    k_reg2<<<dim3(WO / 32, HO / 8, DSLICE), 256>>>(w_reg2);

    // 7: disparity regression
    k_final<<<(HO * WO) / 256, 256>>>(out);
}

// round 14
// speedup vs baseline: 2.9713x; 1.1840x over previous
#include <cuda_runtime.h>
#include <cuda_fp16.h>
#include <cstdint>
#include <math.h>

// ---------------- problem constants ----------------
#define CAMS   4
#define DSLICE 4      // D = NDISP/2
#define NDISP  8
#define IH     640
#define IW     1280
#define FH     320
#define FW     640
#define C1     32
#define HO     256
#define WO     256
#define CF     128    // fused cost channels
#define C2     64
#define C3     32

#define PK1    (CF + 8)    // padded K (elements) conv1
#define PK2    (C2 + 8)    // padded K conv2

// ---------------- scratch (static device memory; no allocs) ----------------
__device__ __half g_feat [(size_t)CAMS*FH*FW*C1];             // fp16 [cam][y][x][c]
__device__ __half g_warp [(size_t)CAMS*DSLICE*FH*FW*C1];      // fp16 [cam][d][y][x][c]
__device__ __half g_costs[(size_t)DSLICE*HO*WO*CF];           // fp16 cost volume [d][h][w][c]
__device__ __half g_x1   [(size_t)DSLICE*HO*WO*C2];           // fp16
__device__ float  g_x2   [(size_t)DSLICE*HO*WO*C3];
__device__ float  g_x3   [(size_t)DSLICE*HO*WO];
__device__ __half g_wB1  [27*C2*PK1];   // conv1 weights fp16 [tap][n][PK1]
__device__ __half g_wB2  [27*C3*PK2];   // conv2 weights fp16 [tap][n][PK2]

// =====================================================================
// helpers
// =====================================================================
__device__ __forceinline__ uint32_t smem_u32(const void* p) {
    uint32_t a;
    asm("{ .reg .u64 t; cvta.to.shared.u64 t, %1; cvt.u32.u64 %0, t; }" : "=r"(a) : "l"(p));
    return a;
}
__device__ __forceinline__ uint32_t lds32(uint32_t addr) {
    uint32_t r;
    asm volatile("ld.shared.b32 %0, [%1];" : "=r"(r) : "r"(addr));
    return r;
}
__device__ __forceinline__ void cp_async16(uint32_t dst, const void* src, bool valid) {
    int sz = valid ? 16 : 0;
    asm volatile("cp.async.cg.shared.global [%0], [%1], 16, %2;"
                 :: "r"(dst), "l"(src), "r"(sz) : "memory");
}
__device__ __forceinline__ void cp_commit() {
    asm volatile("cp.async.commit_group;" ::: "memory");
}
__device__ __forceinline__ void cp_wait0() {
    asm volatile("cp.async.wait_group 0;" ::: "memory");
}
__device__ __forceinline__ void mma_f16(float& d0, float& d1, float& d2, float& d3,
                                        uint32_t a0, uint32_t a1, uint32_t a2, uint32_t a3,
                                        uint32_t b0, uint32_t b1)
{
    asm volatile(
        "mma.sync.aligned.m16n8k16.row.col.f32.f16.f16.f32 "
        "{%0,%1,%2,%3}, {%4,%5,%6,%7}, {%8,%9}, {%0,%1,%2,%3};"
        : "+f"(d0), "+f"(d1), "+f"(d2), "+f"(d3)
        : "r"(a0), "r"(a1), "r"(a2), "r"(a3), "r"(b0), "r"(b1));
}
// 8 halves (uint4) -> 8 floats
__device__ __forceinline__ void h8_to_f8(uint4 v, float* f) {
    float2 t;
    t = __half22float2(*(__half2*)&v.x); f[0] = t.x; f[1] = t.y;
    t = __half22float2(*(__half2*)&v.y); f[2] = t.x; f[3] = t.y;
    t = __half22float2(*(__half2*)&v.z); f[4] = t.x; f[5] = t.y;
    t = __half22float2(*(__half2*)&v.w); f[6] = t.x; f[7] = t.y;
}
__device__ __forceinline__ uint4 f8_to_h8(const float* f) {
    uint4 v;
    __half2 t;
    t = __floats2half2_rn(f[0], f[1]); v.x = *(uint32_t*)&t;
    t = __floats2half2_rn(f[2], f[3]); v.y = *(uint32_t*)&t;
    t = __floats2half2_rn(f[4], f[5]); v.z = *(uint32_t*)&t;
    t = __floats2half2_rn(f[6], f[7]); v.w = *(uint32_t*)&t;
    return v;
}

// ---------------- K1: conv2d 3->32 s2 + relu (grid.z<4) fused with weight prep (grid.z==4) ----
__global__ void k_feat4w(const float* __restrict__ c0, const float* __restrict__ c1,
                         const float* __restrict__ c2, const float* __restrict__ c3,
                         const float* __restrict__ w,
                         const float* __restrict__ w_fusion, const float* __restrict__ w_reg1)
{
    int tid = threadIdx.y * 16 + threadIdx.x;
    int zi  = blockIdx.z;

    if (zi == 4) {
        int idx0   = (blockIdx.y * (FW / 16) + blockIdx.x) * 256 + tid;
        int stride = (FW / 16) * (FH / 16) * 256;
        for (int i = idx0; i < 27 * C2 * CF; i += stride) {
            int k = i % CF;
            int n = (i / CF) % C2;
            int t = i / (CF * C2);
            int kw = t % 3, kh = (t / 3) % 3, kd = t / 9;
            float v = w_fusion[((((size_t)n * CF + k) * 3 + kd) * 3 + kh) * 3 + kw];
            g_wB1[((size_t)t * C2 + n) * PK1 + k] = __float2half(v);
        }
        for (int i = idx0; i < 27 * C3 * C2; i += stride) {
            int k = i % C2;
            int n = (i / C2) % C3;
            int t = i / (C2 * C3);
            int kw = t % 3, kh = (t / 3) % 3, kd = t / 9;
            float v = w_reg1[((((size_t)n * C2 + k) * 3 + kd) * 3 + kh) * 3 + kw];
            g_wB2[((size_t)t * C3 + n) * PK2 + k] = __float2half(v);
        }
        return;
    }

    __shared__ float ws[27 * 32];
    for (int i = tid; i < 864; i += 256) {
        int k = i >> 5, oc = i & 31;
        ws[i] = w[oc * 27 + k];
    }
    __syncthreads();

    const float* cam = (zi == 0) ? c0 : (zi == 1) ? c1 : (zi == 2) ? c2 : c3;
    int ow = blockIdx.x * 16 + threadIdx.x;
    int oh = blockIdx.y * 16 + threadIdx.y;

    float v[27];
#pragma unroll
    for (int ic = 0; ic < 3; ic++)
#pragma unroll
        for (int kh = 0; kh < 3; kh++)
#pragma unroll
            for (int kw = 0; kw < 3; kw++) {
                int iy = 2 * oh + kh - 1;
                int ix = 2 * ow + kw - 1;
                float t = 0.f;
                if (iy >= 0 && iy < IH && ix >= 0 && ix < IW)
                    t = cam[(size_t)ic * IH * IW + (size_t)iy * IW + ix];
                v[ic * 9 + kh * 3 + kw] = t;
            }

    float4 acc[8];
#pragma unroll
    for (int q = 0; q < 8; q++) acc[q] = make_float4(0.f, 0.f, 0.f, 0.f);
    const float4* ws4 = (const float4*)ws;
#pragma unroll
    for (int k = 0; k < 27; k++) {
        float vv = v[k];
#pragma unroll
        for (int q = 0; q < 8; q++) {
            float4 wv = ws4[k * 8 + q];
            acc[q].x += vv * wv.x;  acc[q].y += vv * wv.y;
            acc[q].z += vv * wv.z;  acc[q].w += vv * wv.w;
        }
    }
    __half* o = g_feat + ((size_t)zi * FH * FW + (size_t)oh * FW + ow) * C1;
#pragma unroll
    for (int q = 0; q < 4; q++) {
        float f[8];
        f[0] = fmaxf(acc[2*q].x, 0.f);   f[1] = fmaxf(acc[2*q].y, 0.f);
        f[2] = fmaxf(acc[2*q].z, 0.f);   f[3] = fmaxf(acc[2*q].w, 0.f);
        f[4] = fmaxf(acc[2*q+1].x, 0.f); f[5] = fmaxf(acc[2*q+1].y, 0.f);
        f[6] = fmaxf(acc[2*q+1].z, 0.f); f[7] = fmaxf(acc[2*q+1].w, 0.f);
        *(uint4*)(o + q * 8) = f8_to_h8(f);
    }
}

// ---------------- K2: grid_sample fp16, 4 lanes/pixel, 2 d-slices per thread ----------------
__global__ void __launch_bounds__(256)
k_warp(const float* __restrict__ grids)
{
    int tid = threadIdx.x;
    int c   = tid & 3;           // 8-half chunk
    int pid = tid >> 2;          // pixel within block (0..63)
    int pos = blockIdx.x * 64 + pid;
    int d0  = blockIdx.y;
    int cam = blockIdx.z;
    int y = pos / FW, x = pos % FW;

    const __half* fb = g_feat + (size_t)cam * FH * FW * C1 + c * 8;

#pragma unroll
    for (int s = 0; s < 2; s++) {
        int d = d0 + s * 2;
        const float* g = grids + ((((size_t)cam * DSLICE + d) * FH + y) * FW + x) * 2;
        float fx = (g[0] + 1.f) * (FW * 0.5f) - 0.5f;
        float fy = (g[1] + 1.f) * (FH * 0.5f) - 0.5f;
        float x0f = floorf(fx), y0f = floorf(fy);
        float wx = fx - x0f,   wy = fy - y0f;
        int x0 = (int)x0f, y0 = (int)y0f;
        int x1 = x0 + 1,   y1 = y0 + 1;
        float vx0 = (x0 >= 0 && x0 < FW) ? 1.f : 0.f;
        float vx1 = (x1 >= 0 && x1 < FW) ? 1.f : 0.f;
        float vy0 = (y0 >= 0 && y0 < FH) ? 1.f : 0.f;
        float vy1 = (y1 >= 0 && y1 < FH) ? 1.f : 0.f;
        float w00 = (1.f - wx) * (1.f - wy) * vx0 * vy0;
        float w01 = wx * (1.f - wy) * vx1 * vy0;
        float w10 = (1.f - wx) * wy * vx0 * vy1;
        float w11 = wx * wy * vx1 * vy1;
        int x0c = min(max(x0, 0), FW - 1), x1c = min(max(x1, 0), FW - 1);
        int y0c = min(max(y0, 0), FH - 1), y1c = min(max(y1, 0), FH - 1);

        uint4 ra = *(const uint4*)(fb + ((size_t)y0c * FW + x0c) * C1);
        uint4 rb = *(const uint4*)(fb + ((size_t)y0c * FW + x1c) * C1);
        uint4 re = *(const uint4*)(fb + ((size_t)y1c * FW + x0c) * C1);
        uint4 rf = *(const uint4*)(fb + ((size_t)y1c * FW + x1c) * C1);
        float a[8], b[8], e[8], f[8], r[8];
        h8_to_f8(ra, a); h8_to_f8(rb, b); h8_to_f8(re, e); h8_to_f8(rf, f);
#pragma unroll
        for (int q = 0; q < 8; q++)
            r[q] = w00 * a[q] + w01 * b[q] + w10 * e[q] + w11 * f[q];
        *(uint4*)(g_warp + ((size_t)(cam * DSLICE + d) * FH * FW + pos) * C1 + c * 8) = f8_to_h8(r);
    }
}

// ---------------- K3: antialiased resize fp16, 4 lanes/pixel ----------------
__global__ void __launch_bounds__(256)
k_resize()
{
    int tid  = threadIdx.x;
    int c    = tid & 3;
    int pid  = tid >> 2;
    int opos = blockIdx.x * 64 + pid;
    int ho   = opos >> 8;
    int wo   = opos & 255;
    int d    = blockIdx.y;
    int cam  = blockIdx.z;

    float sy = (ho + 0.5f) * 1.25f - 0.5f;
    int jy0 = max((int)ceilf(sy - 1.25f), 0);
    int jy1 = min((int)floorf(sy + 1.25f), FH - 1);
    float wyv[4]; int ny = jy1 - jy0 + 1;
    float sumy = 0.f;
    for (int i = 0; i < ny; i++) {
        float w = fmaxf(1.f - fabsf(sy - (float)(jy0 + i)) * 0.8f, 0.f);
        wyv[i] = w; sumy += w;
    }
    for (int i = 0; i < ny; i++) wyv[i] /= sumy;

    float sx = (wo + 0.5f) * 2.5f - 0.5f;
    int jx0 = max((int)ceilf(sx - 2.5f), 0);
    int jx1 = min((int)floorf(sx + 2.5f), FW - 1);
    float wxv[6]; int nx = jx1 - jx0 + 1;
    float sumx = 0.f;
    for (int i = 0; i < nx; i++) {
        float w = fmaxf(1.f - fabsf(sx - (float)(jx0 + i)) * 0.4f, 0.f);
        wxv[i] = w; sumx += w;
    }
    for (int i = 0; i < nx; i++) wxv[i] /= sumx;

    float acc[8];
#pragma unroll
    for (int q = 0; q < 8; q++) acc[q] = 0.f;
    const __half* base = g_warp + (size_t)(cam * DSLICE + d) * FH * FW * C1 + c * 8;
    for (int iy = 0; iy < ny; iy++) {
        const __half* rowb = base + (size_t)(jy0 + iy) * FW * C1;
        for (int ix = 0; ix < nx; ix++) {
            float wgt = wyv[iy] * wxv[ix];
            float t[8];
            h8_to_f8(*(const uint4*)(rowb + (size_t)(jx0 + ix) * C1), t);
#pragma unroll
            for (int q = 0; q < 8; q++) acc[q] += wgt * t[q];
        }
    }
    size_t obase = (((size_t)d * HO + ho) * WO + wo) * CF + cam * C1 + c * 8;
    *(uint4*)(g_costs + obase) = f8_to_h8(acc);
}

// ---------------- K4: conv3d 3x3x3 pad1 + relu, single-term fp16, B double-buffered ----------
// 128 threads / 4 warps. A single-buffered, B 2 slots -> B staging hidden under compute.
// conv1: MI=4, NWN=2 (warp M64xN32). conv2: MI=2, NWN=1 (warp M32xN32).
template<int CIN, int COUT, int MI, int NWN, bool OBF>
__global__ void __launch_bounds__(128)
k_conv3d_mma(const __half* __restrict__ in, const __half* __restrict__ wB,
             __half* __restrict__ out_hlf, float* __restrict__ out_f)
{
    constexpr int NT   = 128;
    constexpr int PK   = CIN + 8;
    constexpr int PKB  = PK * 2;             // bytes per smem row
    constexpr int SA   = 130 * PKB;          // A plane bytes
    constexpr int TB   = COUT * PKB;         // B tap bytes
    constexpr int NJ   = (COUT / NWN) / 8;   // 4
    constexpr int KST  = CIN / 16;           // k-steps per item
    constexpr int CH   = CIN / 8;            // 16B chunks per A row

    extern __shared__ char dsm[];
    const uint32_t sBase = smem_u32(dsm);
    const uint32_t sA  = sBase;              // [A | B0 | B1]
    const uint32_t sB0 = sBase + SA;

    int tid  = threadIdx.x;
    int wid  = tid >> 5, lane = tid & 31;
    int gid  = lane >> 2, tig = lane & 3;
    int wM   = wid / NWN;
    int wN   = wid % NWN;
    int ow0  = blockIdx.x * 128;
    int oh   = blockIdx.y, od = blockIdx.z;

    // ---- build valid (kd,kh) list ----
    int zdv[9], zhv[9], t9v[9];
    int nv = 0;
    for (int kd = 0; kd < 3; kd++) {
        int zd = od + kd - 1;
        if (zd < 0 || zd >= DSLICE) continue;
        for (int kh = 0; kh < 3; kh++) {
            int zh = oh + kh - 1;
            if (zh < 0 || zh >= HO) continue;
            zdv[nv] = zd; zhv[nv] = zh; t9v[nv] = kd * 3 + kh;
            nv++;
        }
    }
    int nitems = nv * 3;

    float acc[MI][NJ][4];
#pragma unroll
    for (int mi = 0; mi < MI; mi++)
#pragma unroll
        for (int nj = 0; nj < NJ; nj++)
#pragma unroll
            for (int cc = 0; cc < 4; cc++) acc[mi][nj][cc] = 0.f;

    auto stage_A = [&](int ai) {
        size_t inoff = ((size_t)zdv[ai] * HO + zhv[ai]) * WO * CIN;
        for (int i = tid; i < 130 * CH; i += NT) {
            int r = i / CH, g = i % CH;
            int p = ow0 - 1 + r;
            bool v = (p >= 0 && p < WO);
            int pc = v ? p : 0;
            cp_async16(sA + (uint32_t)r * PKB + g * 16,
                       in + inoff + (size_t)pc * CIN + g * 8, v);
        }
    };
    auto stage_B = [&](int slot, int j) {
        int t = t9v[j / 3] * 3 + (j % 3);
        const char* src = (const char*)(wB + (size_t)t * COUT * PK);
        uint32_t dB = sB0 + (uint32_t)slot * TB;
        for (int i = tid; i < TB / 16; i += NT)
            cp_async16(dB + i * 16, src + i * 16, true);
    };

    // prologue
    stage_A(0);
    stage_B(0, 0);
    cp_commit();
    cp_wait0();
    __syncthreads();

    for (int j = 0; j < nitems; j++) {
        int jn = j + 1;
        // issue next B into the other slot (hidden under this item's compute)
        if (jn < nitems) {
            stage_B(jn & 1, jn);
            cp_commit();
        }

        int q = j % 3;
        uint32_t aB0 = sA + (uint32_t)(q + wM * (MI * 16) + gid) * PKB + tig * 4;
        uint32_t bB0 = sB0 + (uint32_t)(j & 1) * TB + (uint32_t)(wN * 32 + gid) * PKB + tig * 4;
#pragma unroll
        for (int ks = 0; ks < KST; ks++) {
            uint32_t ko = (uint32_t)ks * 32;
            uint32_t av[MI][4], bv[NJ][2];
#pragma unroll
            for (int mi = 0; mi < MI; mi++) {
                uint32_t a = aB0 + mi * 16 * PKB + ko;
                av[mi][0] = lds32(a);
                av[mi][1] = lds32(a + 8 * PKB);
                av[mi][2] = lds32(a + 16);
                av[mi][3] = lds32(a + 8 * PKB + 16);
            }
#pragma unroll
            for (int nj = 0; nj < NJ; nj++) {
                uint32_t bb = bB0 + nj * 8 * PKB + ko;
                bv[nj][0] = lds32(bb);
                bv[nj][1] = lds32(bb + 16);
            }
#pragma unroll
            for (int nj = 0; nj < NJ; nj++)
#pragma unroll
                for (int mi = 0; mi < MI; mi++)
                    mma_f16(acc[mi][nj][0], acc[mi][nj][1], acc[mi][nj][2], acc[mi][nj][3],
                            av[mi][0], av[mi][1], av[mi][2], av[mi][3],
                            bv[nj][0], bv[nj][1]);
        }
        __syncthreads();   // all warps done reading A (and old B slot)

        if (jn < nitems) {
            if (jn % 3 == 0) {
                stage_A(jn / 3);             // A buffer free now
                cp_commit();
            }
            cp_wait0();                      // B(jn) (+A) complete
            __syncthreads();
        }
    }

    // ---- epilogue: relu + store ----
#pragma unroll
    for (int mi = 0; mi < MI; mi++) {
        int row = wM * (MI * 16) + mi * 16 + gid;
        size_t base0 = (((size_t)od * HO + oh) * WO + ow0 + row) * COUT;
        size_t base1 = base0 + 8 * COUT;      // row + 8
#pragma unroll
        for (int nj = 0; nj < NJ; nj++) {
            int col = wN * 32 + nj * 8 + tig * 2;
            float v00 = fmaxf(acc[mi][nj][0], 0.f);
            float v01 = fmaxf(acc[mi][nj][1], 0.f);
            float v10 = fmaxf(acc[mi][nj][2], 0.f);
            float v11 = fmaxf(acc[mi][nj][3], 0.f);
            if (OBF) {
                __half2 p0 = __floats2half2_rn(v00, v01);
                __half2 p1 = __floats2half2_rn(v10, v11);
                *(uint32_t*)(out_hlf + base0 + col) = *(uint32_t*)&p0;
                *(uint32_t*)(out_hlf + base1 + col) = *(uint32_t*)&p1;
            } else {
                *(float2*)(out_f + base0 + col) = make_float2(v00, v01);
                *(float2*)(out_f + base1 + col) = make_float2(v10, v11);
            }
        }
    }
}

// ---------------- K5: conv3d 32->1 (no relu), smem-tiled ----------------
__global__ void __launch_bounds__(256)
k_reg2(const float* __restrict__ w2)
{
    __shared__ float ws_t[27 * 32];                 // [k27][ic32]
    __shared__ float tile[10][34][32];              // [zh][zw][c]
    int tx = threadIdx.x & 31;
    int ty = threadIdx.x >> 5;
    int tid = threadIdx.x;
    for (int i = tid; i < 864; i += 256) {
        int ic = i / 27, k = i % 27;
        ws_t[k * 32 + ic] = w2[i];
    }

    int ow0 = blockIdx.x * 32;
    int oh0 = blockIdx.y * 8;
    int od  = blockIdx.z;
    int ow = ow0 + tx, oh = oh0 + ty;

    float acc = 0.f;
    for (int kd = 0; kd < 3; kd++) {
        int zd = od + kd - 1;
        if (zd < 0 || zd >= DSLICE) continue;
        __syncthreads();
        for (int i = tid; i < 10 * 34 * 8; i += 256) {
            int g  = i & 7;
            int zw = (i >> 3) % 34 + ow0 - 1;
            int zh = (i >> 3) / 34 + oh0 - 1;
            bool v = (zw >= 0 && zw < WO && zh >= 0 && zh < HO);
            int zwc = v ? zw : 0, zhc = v ? zh : 0;
            const float* src = g_x2 + (((size_t)zd * HO + zhc) * WO + zwc) * C3 + g * 4;
            cp_async16(smem_u32(&tile[(i >> 3) / 34][(i >> 3) % 34][g * 4]), src, v);
        }
        cp_commit();
        cp_wait0();
        __syncthreads();

#pragma unroll
        for (int kh = 0; kh < 3; kh++) {
#pragma unroll
            for (int kw = 0; kw < 3; kw++) {
                int k = kd * 9 + kh * 3 + kw;
                const float4* p  = (const float4*)&tile[ty + kh][tx + kw][0];
                const float4* wv = (const float4*)&ws_t[k * 32];
#pragma unroll
                for (int qq = 0; qq < 8; qq++) {
                    float4 a = p[qq], b = wv[qq];
                    acc += a.x * b.x + a.y * b.y + a.z * b.z + a.w * b.w;
                }
            }
        }
    }
    g_x3[((size_t)od * HO + oh) * WO + ow] = acc;
}

// ---------------- K6: D-resize 4->8 + softmax + expectation ----------------
__global__ void k_final(float* __restrict__ outp)
{
    int pos = blockIdx.x * 256 + threadIdx.x;
    float v[4];
#pragma unroll
    for (int d = 0; d < 4; d++) v[d] = g_x3[(size_t)d * (HO * WO) + pos];

    float y[8];
#pragma unroll
    for (int o = 0; o < 8; o++) {
        float s = 0.5f * o - 0.25f;
        int j0 = max(0, (int)ceilf(s - 1.f));
        int j1 = min(3, (int)floorf(s + 1.f));
        float acc = 0.f, wsum = 0.f;
        for (int j = j0; j <= j1; j++) {
            float w = fmaxf(1.f - fabsf(s - (float)j), 0.f);
            acc += w * v[j]; wsum += w;
        }
        y[o] = acc / wsum;
    }
    float m = y[0];
#pragma unroll
    for (int o = 1; o < 8; o++) m = fmaxf(m, y[o]);
    float esum = 0.f, dsum = 0.f;
#pragma unroll
    for (int o = 0; o < 8; o++) {
        float e = expf(y[o] - m);
        esum += e;
        dsum += e * (float)o;
    }
    outp[pos] = dsum / esum;
}

// ---------------- host launch ----------------
extern "C" void kernel_launch(void* const* d_in, const int* in_sizes, int n_in,
                              void* d_out, int out_size)
{
    const float* cams[4] = { (const float*)d_in[0], (const float*)d_in[1],
                             (const float*)d_in[2], (const float*)d_in[3] };
    const float* grids    = (const float*)d_in[4];
    const float* w_feat   = (const float*)d_in[5];
    const float* w_fusion = (const float*)d_in[6];
    const float* w_reg1   = (const float*)d_in[7];
    const float* w_reg2   = (const float*)d_in[8];
    float* out = (float*)d_out;

    __half *p_wB1, *p_wB2, *p_costs, *p_x1;
    float* p_x2;
    cudaGetSymbolAddress((void**)&p_x2,    g_x2);
    cudaGetSymbolAddress((void**)&p_wB1,   g_wB1);
    cudaGetSymbolAddress((void**)&p_wB2,   g_wB2);
    cudaGetSymbolAddress((void**)&p_costs, g_costs);
    cudaGetSymbolAddress((void**)&p_x1,    g_x1);

    // A + 2 B slots (fp16)
    const int SMEM1 = 130 * PK1 * 2 + 2 * C2 * PK1 * 2;   // 35360 + 34816 = 70176 -> 3 CTAs/SM
    const int SMEM2 = 130 * PK2 * 2 + 2 * C3 * PK2 * 2;   // 18720 +  9216 = 27936
    cudaFuncSetAttribute((const void*)k_conv3d_mma<CF, C2, 4, 2, true>,
                         cudaFuncAttributeMaxDynamicSharedMemorySize, SMEM1);
    cudaFuncSetAttribute((const void*)k_conv3d_mma<C2, C3, 2, 1, false>,
                         cudaFuncAttributeMaxDynamicSharedMemorySize, SMEM2);

    // 1: feature extraction + weight prep (fused)
    k_feat4w<<<dim3(FW / 16, FH / 16, 5), dim3(16, 16)>>>(
        cams[0], cams[1], cams[2], cams[3], w_feat, w_fusion, w_reg1);

    // 2: plane sweep warp (fp16 path, 2 d per thread)
    k_warp<<<dim3(FH * FW / 64, 2, CAMS), 256>>>(grids);

    // 3: antialiased resize -> fp16 cost volume
    k_resize<<<dim3(HO * WO / 64, DSLICE, CAMS), 256>>>();

    // 4: conv1 (profiled launch)  5: conv2 — fp16 single-term, B double-buffered
    k_conv3d_mma<CF, C2, 4, 2, true ><<<dim3(WO / 128, HO, DSLICE), 128, SMEM1>>>(p_costs, p_wB1, p_x1, nullptr);
    k_conv3d_mma<C2, C3, 2, 1, false><<<dim3(WO / 128, HO, DSLICE), 128, SMEM2>>>(p_x1, p_wB2, nullptr, p_x2);

    // 6: squeeze conv
    k_reg2<<<dim3(WO / 32, HO / 8, DSLICE), 256>>>(w_reg2);

    // 7: disparity regression
    k_final<<<(HO * WO) / 256, 256>>>(out);
}

// round 15
// speedup vs baseline: 3.4745x; 1.1694x over previous
#include <cuda_runtime.h>
#include <cuda_fp16.h>
#include <cstdint>
#include <math.h>

// ---------------- problem constants ----------------
#define CAMS   4
#define DSLICE 4      // D = NDISP/2
#define NDISP  8
#define IH     640
#define IW     1280
#define FH     320
#define FW     640
#define C1     32
#define HO     256
#define WO     256
#define CF     128    // fused cost channels
#define C2     64
#define C3     32

#define PK1    (CF + 8)    // padded K (elements) conv1
#define PK2    (C2 + 8)    // padded K conv2

// ---------------- scratch (static device memory; no allocs) ----------------
__device__ __half g_feat [(size_t)CAMS*FH*FW*C1];             // fp16 [cam][y][x][c]
__device__ __half g_warp [(size_t)CAMS*DSLICE*FH*FW*C1];      // fp16 [cam][d][y][x][c]
__device__ __half g_costs[(size_t)DSLICE*HO*WO*CF];           // fp16 cost volume [d][h][w][c]
__device__ __half g_x1   [(size_t)DSLICE*HO*WO*C2];           // fp16
__device__ __half g_x2   [(size_t)DSLICE*HO*WO*C3];           // fp16
__device__ float  g_x3   [(size_t)DSLICE*HO*WO];
__device__ __half g_wB1  [27*C2*PK1];   // conv1 weights fp16 [tap][n][PK1]
__device__ __half g_wB2  [27*C3*PK2];   // conv2 weights fp16 [tap][n][PK2]

// =====================================================================
// helpers
// =====================================================================
__device__ __forceinline__ uint32_t smem_u32(const void* p) {
    uint32_t a;
    asm("{ .reg .u64 t; cvta.to.shared.u64 t, %1; cvt.u32.u64 %0, t; }" : "=r"(a) : "l"(p));
    return a;
}
__device__ __forceinline__ uint32_t lds32(uint32_t addr) {
    uint32_t r;
    asm volatile("ld.shared.b32 %0, [%1];" : "=r"(r) : "r"(addr));
    return r;
}
__device__ __forceinline__ void cp_async16(uint32_t dst, const void* src, bool valid) {
    int sz = valid ? 16 : 0;
    asm volatile("cp.async.cg.shared.global [%0], [%1], 16, %2;"
                 :: "r"(dst), "l"(src), "r"(sz) : "memory");
}
__device__ __forceinline__ void cp_commit() {
    asm volatile("cp.async.commit_group;" ::: "memory");
}
__device__ __forceinline__ void cp_wait0() {
    asm volatile("cp.async.wait_group 0;" ::: "memory");
}
__device__ __forceinline__ void mma_f16(float& d0, float& d1, float& d2, float& d3,
                                        uint32_t a0, uint32_t a1, uint32_t a2, uint32_t a3,
                                        uint32_t b0, uint32_t b1)
{
    asm volatile(
        "mma.sync.aligned.m16n8k16.row.col.f32.f16.f16.f32 "
        "{%0,%1,%2,%3}, {%4,%5,%6,%7}, {%8,%9}, {%0,%1,%2,%3};"
        : "+f"(d0), "+f"(d1), "+f"(d2), "+f"(d3)
        : "r"(a0), "r"(a1), "r"(a2), "r"(a3), "r"(b0), "r"(b1));
}
// 8 halves (uint4) -> 8 floats
__device__ __forceinline__ void h8_to_f8(uint4 v, float* f) {
    float2 t;
    t = __half22float2(*(__half2*)&v.x); f[0] = t.x; f[1] = t.y;
    t = __half22float2(*(__half2*)&v.y); f[2] = t.x; f[3] = t.y;
    t = __half22float2(*(__half2*)&v.z); f[4] = t.x; f[5] = t.y;
    t = __half22float2(*(__half2*)&v.w); f[6] = t.x; f[7] = t.y;
}
__device__ __forceinline__ uint4 f8_to_h8(const float* f) {
    uint4 v;
    __half2 t;
    t = __floats2half2_rn(f[0], f[1]); v.x = *(uint32_t*)&t;
    t = __floats2half2_rn(f[2], f[3]); v.y = *(uint32_t*)&t;
    t = __floats2half2_rn(f[4], f[5]); v.z = *(uint32_t*)&t;
    t = __floats2half2_rn(f[6], f[7]); v.w = *(uint32_t*)&t;
    return v;
}

// ---------------- K1: conv2d 3->32 s2 + relu (grid.z<4) fused with weight prep (grid.z==4) ----
__global__ void k_feat4w(const float* __restrict__ c0, const float* __restrict__ c1,
                         const float* __restrict__ c2, const float* __restrict__ c3,
                         const float* __restrict__ w,
                         const float* __restrict__ w_fusion, const float* __restrict__ w_reg1)
{
    int tid = threadIdx.y * 16 + threadIdx.x;
    int zi  = blockIdx.z;

    if (zi == 4) {
        int idx0   = (blockIdx.y * (FW / 16) + blockIdx.x) * 256 + tid;
        int stride = (FW / 16) * (FH / 16) * 256;
        for (int i = idx0; i < 27 * C2 * CF; i += stride) {
            int k = i % CF;
            int n = (i / CF) % C2;
            int t = i / (CF * C2);
            int kw = t % 3, kh = (t / 3) % 3, kd = t / 9;
            float v = w_fusion[((((size_t)n * CF + k) * 3 + kd) * 3 + kh) * 3 + kw];
            g_wB1[((size_t)t * C2 + n) * PK1 + k] = __float2half(v);
        }
        for (int i = idx0; i < 27 * C3 * C2; i += stride) {
            int k = i % C2;
            int n = (i / C2) % C3;
            int t = i / (C2 * C3);
            int kw = t % 3, kh = (t / 3) % 3, kd = t / 9;
            float v = w_reg1[((((size_t)n * C2 + k) * 3 + kd) * 3 + kh) * 3 + kw];
            g_wB2[((size_t)t * C3 + n) * PK2 + k] = __float2half(v);
        }
        return;
    }

    __shared__ float ws[27 * 32];
    for (int i = tid; i < 864; i += 256) {
        int k = i >> 5, oc = i & 31;
        ws[i] = w[oc * 27 + k];
    }
    __syncthreads();

    const float* cam = (zi == 0) ? c0 : (zi == 1) ? c1 : (zi == 2) ? c2 : c3;
    int ow = blockIdx.x * 16 + threadIdx.x;
    int oh = blockIdx.y * 16 + threadIdx.y;

    float v[27];
#pragma unroll
    for (int ic = 0; ic < 3; ic++)
#pragma unroll
        for (int kh = 0; kh < 3; kh++)
#pragma unroll
            for (int kw = 0; kw < 3; kw++) {
                int iy = 2 * oh + kh - 1;
                int ix = 2 * ow + kw - 1;
                float t = 0.f;
                if (iy >= 0 && iy < IH && ix >= 0 && ix < IW)
                    t = cam[(size_t)ic * IH * IW + (size_t)iy * IW + ix];
                v[ic * 9 + kh * 3 + kw] = t;
            }

    float4 acc[8];
#pragma unroll
    for (int q = 0; q < 8; q++) acc[q] = make_float4(0.f, 0.f, 0.f, 0.f);
    const float4* ws4 = (const float4*)ws;
#pragma unroll
    for (int k = 0; k < 27; k++) {
        float vv = v[k];
#pragma unroll
        for (int q = 0; q < 8; q++) {
            float4 wv = ws4[k * 8 + q];
            acc[q].x += vv * wv.x;  acc[q].y += vv * wv.y;
            acc[q].z += vv * wv.z;  acc[q].w += vv * wv.w;
        }
    }
    __half* o = g_feat + ((size_t)zi * FH * FW + (size_t)oh * FW + ow) * C1;
#pragma unroll
    for (int q = 0; q < 4; q++) {
        float f[8];
        f[0] = fmaxf(acc[2*q].x, 0.f);   f[1] = fmaxf(acc[2*q].y, 0.f);
        f[2] = fmaxf(acc[2*q].z, 0.f);   f[3] = fmaxf(acc[2*q].w, 0.f);
        f[4] = fmaxf(acc[2*q+1].x, 0.f); f[5] = fmaxf(acc[2*q+1].y, 0.f);
        f[6] = fmaxf(acc[2*q+1].z, 0.f); f[7] = fmaxf(acc[2*q+1].w, 0.f);
        *(uint4*)(o + q * 8) = f8_to_h8(f);
    }
}

// ---------------- K2: grid_sample fp16, 4 lanes/pixel, 2 d-slices per thread ----------------
__global__ void __launch_bounds__(256)
k_warp(const float* __restrict__ grids)
{
    int tid = threadIdx.x;
    int c   = tid & 3;           // 8-half chunk
    int pid = tid >> 2;          // pixel within block (0..63)
    int pos = blockIdx.x * 64 + pid;
    int d0  = blockIdx.y;
    int cam = blockIdx.z;
    int y = pos / FW, x = pos % FW;

    const __half* fb = g_feat + (size_t)cam * FH * FW * C1 + c * 8;

#pragma unroll
    for (int s = 0; s < 2; s++) {
        int d = d0 + s * 2;
        const float* g = grids + ((((size_t)cam * DSLICE + d) * FH + y) * FW + x) * 2;
        float fx = (g[0] + 1.f) * (FW * 0.5f) - 0.5f;
        float fy = (g[1] + 1.f) * (FH * 0.5f) - 0.5f;
        float x0f = floorf(fx), y0f = floorf(fy);
        float wx = fx - x0f,   wy = fy - y0f;
        int x0 = (int)x0f, y0 = (int)y0f;
        int x1 = x0 + 1,   y1 = y0 + 1;
        float vx0 = (x0 >= 0 && x0 < FW) ? 1.f : 0.f;
        float vx1 = (x1 >= 0 && x1 < FW) ? 1.f : 0.f;
        float vy0 = (y0 >= 0 && y0 < FH) ? 1.f : 0.f;
        float vy1 = (y1 >= 0 && y1 < FH) ? 1.f : 0.f;
        float w00 = (1.f - wx) * (1.f - wy) * vx0 * vy0;
        float w01 = wx * (1.f - wy) * vx1 * vy0;
        float w10 = (1.f - wx) * wy * vx0 * vy1;
        float w11 = wx * wy * vx1 * vy1;
        int x0c = min(max(x0, 0), FW - 1), x1c = min(max(x1, 0), FW - 1);
        int y0c = min(max(y0, 0), FH - 1), y1c = min(max(y1, 0), FH - 1);

        uint4 ra = *(const uint4*)(fb + ((size_t)y0c * FW + x0c) * C1);
        uint4 rb = *(const uint4*)(fb + ((size_t)y0c * FW + x1c) * C1);
        uint4 re = *(const uint4*)(fb + ((size_t)y1c * FW + x0c) * C1);
        uint4 rf = *(const uint4*)(fb + ((size_t)y1c * FW + x1c) * C1);
        float a[8], b[8], e[8], f[8], r[8];
        h8_to_f8(ra, a); h8_to_f8(rb, b); h8_to_f8(re, e); h8_to_f8(rf, f);
#pragma unroll
        for (int q = 0; q < 8; q++)
            r[q] = w00 * a[q] + w01 * b[q] + w10 * e[q] + w11 * f[q];
        *(uint4*)(g_warp + ((size_t)(cam * DSLICE + d) * FH * FW + pos) * C1 + c * 8) = f8_to_h8(r);
    }
}

// ---------------- K3: antialiased resize fp16, 4 lanes/pixel ----------------
__global__ void __launch_bounds__(256)
k_resize()
{
    int tid  = threadIdx.x;
    int c    = tid & 3;
    int pid  = tid >> 2;
    int opos = blockIdx.x * 64 + pid;
    int ho   = opos >> 8;
    int wo   = opos & 255;
    int d    = blockIdx.y;
    int cam  = blockIdx.z;

    float sy = (ho + 0.5f) * 1.25f - 0.5f;
    int jy0 = max((int)ceilf(sy - 1.25f), 0);
    int jy1 = min((int)floorf(sy + 1.25f), FH - 1);
    float wyv[4]; int ny = jy1 - jy0 + 1;
    float sumy = 0.f;
    for (int i = 0; i < ny; i++) {
        float w = fmaxf(1.f - fabsf(sy - (float)(jy0 + i)) * 0.8f, 0.f);
        wyv[i] = w; sumy += w;
    }
    for (int i = 0; i < ny; i++) wyv[i] /= sumy;

    float sx = (wo + 0.5f) * 2.5f - 0.5f;
    int jx0 = max((int)ceilf(sx - 2.5f), 0);
    int jx1 = min((int)floorf(sx + 2.5f), FW - 1);
    float wxv[6]; int nx = jx1 - jx0 + 1;
    float sumx = 0.f;
    for (int i = 0; i < nx; i++) {
        float w = fmaxf(1.f - fabsf(sx - (float)(jx0 + i)) * 0.4f, 0.f);
        wxv[i] = w; sumx += w;
    }
    for (int i = 0; i < nx; i++) wxv[i] /= sumx;

    float acc[8];
#pragma unroll
    for (int q = 0; q < 8; q++) acc[q] = 0.f;
    const __half* base = g_warp + (size_t)(cam * DSLICE + d) * FH * FW * C1 + c * 8;
    for (int iy = 0; iy < ny; iy++) {
        const __half* rowb = base + (size_t)(jy0 + iy) * FW * C1;
        for (int ix = 0; ix < nx; ix++) {
            float wgt = wyv[iy] * wxv[ix];
            float t[8];
            h8_to_f8(*(const uint4*)(rowb + (size_t)(jx0 + ix) * C1), t);
#pragma unroll
            for (int q = 0; q < 8; q++) acc[q] += wgt * t[q];
        }
    }
    size_t obase = (((size_t)d * HO + ho) * WO + wo) * CF + cam * C1 + c * 8;
    *(uint4*)(g_costs + obase) = f8_to_h8(acc);
}

// ---------------- K4: conv3d 3x3x3 pad1 + relu, fp16 mma, A+B double-buffered ---------------
// 128 threads / 4 warps. Both A (per (kd,kh) group) and B (per tap) ping-pong; all staging
// issued >=1 item before use -> no structurally exposed cp.async waits.
// conv1: MI=4, NWN=2 (warp M64xN32), 105.5 KB -> 2 CTAs/SM.
// conv2: MI=2, NWN=1 (warp M32xN32),  46.7 KB -> 4 CTAs/SM.
template<int CIN, int COUT, int MI, int NWN>
__global__ void __launch_bounds__(128)
k_conv3d_mma(const __half* __restrict__ in, const __half* __restrict__ wB,
             __half* __restrict__ out)
{
    constexpr int NT   = 128;
    constexpr int PK   = CIN + 8;
    constexpr int PKB  = PK * 2;             // bytes per smem row
    constexpr int SA   = 130 * PKB;          // one A slot
    constexpr int TB   = COUT * PKB;         // one B slot
    constexpr int NJ   = (COUT / NWN) / 8;   // 4
    constexpr int KST  = CIN / 16;           // k-steps per item
    constexpr int CH   = CIN / 8;            // 16B chunks per A row

    extern __shared__ char dsm[];
    const uint32_t sBase = smem_u32(dsm);
    const uint32_t sA0 = sBase;              // [A0 | A1 | B0 | B1]
    const uint32_t sB0 = sBase + 2 * SA;

    int tid  = threadIdx.x;
    int wid  = tid >> 5, lane = tid & 31;
    int gid  = lane >> 2, tig = lane & 3;
    int wM   = wid / NWN;
    int wN   = wid % NWN;
    int ow0  = blockIdx.x * 128;
    int oh   = blockIdx.y, od = blockIdx.z;

    // ---- build valid (kd,kh) list ----
    int zdv[9], zhv[9], t9v[9];
    int nv = 0;
    for (int kd = 0; kd < 3; kd++) {
        int zd = od + kd - 1;
        if (zd < 0 || zd >= DSLICE) continue;
        for (int kh = 0; kh < 3; kh++) {
            int zh = oh + kh - 1;
            if (zh < 0 || zh >= HO) continue;
            zdv[nv] = zd; zhv[nv] = zh; t9v[nv] = kd * 3 + kh;
            nv++;
        }
    }
    int nitems = nv * 3;

    float acc[MI][NJ][4];
#pragma unroll
    for (int mi = 0; mi < MI; mi++)
#pragma unroll
        for (int nj = 0; nj < NJ; nj++)
#pragma unroll
            for (int cc = 0; cc < 4; cc++) acc[mi][nj][cc] = 0.f;

    auto stage_A = [&](int slot, int ai) {
        size_t inoff = ((size_t)zdv[ai] * HO + zhv[ai]) * WO * CIN;
        uint32_t dA = sA0 + (uint32_t)slot * SA;
        for (int i = tid; i < 130 * CH; i += NT) {
            int r = i / CH, g = i % CH;
            int p = ow0 - 1 + r;
            bool v = (p >= 0 && p < WO);
            int pc = v ? p : 0;
            cp_async16(dA + (uint32_t)r * PKB + g * 16,
                       in + inoff + (size_t)pc * CIN + g * 8, v);
        }
    };
    auto stage_B = [&](int slot, int j) {
        int t = t9v[j / 3] * 3 + (j % 3);
        const char* src = (const char*)(wB + (size_t)t * COUT * PK);
        uint32_t dB = sB0 + (uint32_t)slot * TB;
        for (int i = tid; i < TB / 16; i += NT)
            cp_async16(dB + i * 16, src + i * 16, true);
    };

    // prologue: stage item 0 (A group 0 + B tap 0), wait
    stage_A(0, 0);
    stage_B(0, 0);
    cp_commit();
    cp_wait0();
    __syncthreads();

    for (int j = 0; j < nitems; j++) {
        int jn = j + 1;
        bool staged = false;
        // issue next B (alternate slot) and, mid-group, next A (alternate slot)
        if (jn < nitems) {
            stage_B(jn & 1, jn);
            staged = true;
        }
        int gn = j / 3 + 1;
        if ((j % 3) == 1 && gn * 3 < nitems) {
            stage_A(gn & 1, gn);
            staged = true;
        }
        if (staged) cp_commit();

        // ---- compute item j ----
        int q = j % 3;
        uint32_t aB0 = sA0 + (uint32_t)((j / 3) & 1) * SA
                     + (uint32_t)(q + wM * (MI * 16) + gid) * PKB + tig * 4;
        uint32_t bB0 = sB0 + (uint32_t)(j & 1) * TB
                     + (uint32_t)(wN * 32 + gid) * PKB + tig * 4;
#pragma unroll
        for (int ks = 0; ks < KST; ks++) {
            uint32_t ko = (uint32_t)ks * 32;
            uint32_t av[MI][4], bv[NJ][2];
#pragma unroll
            for (int mi = 0; mi < MI; mi++) {
                uint32_t a = aB0 + mi * 16 * PKB + ko;
                av[mi][0] = lds32(a);
                av[mi][1] = lds32(a + 8 * PKB);
                av[mi][2] = lds32(a + 16);
                av[mi][3] = lds32(a + 8 * PKB + 16);
            }
#pragma unroll
            for (int nj = 0; nj < NJ; nj++) {
                uint32_t bb = bB0 + nj * 8 * PKB + ko;
                bv[nj][0] = lds32(bb);
                bv[nj][1] = lds32(bb + 16);
            }
#pragma unroll
            for (int nj = 0; nj < NJ; nj++)
#pragma unroll
                for (int mi = 0; mi < MI; mi++)
                    mma_f16(acc[mi][nj][0], acc[mi][nj][1], acc[mi][nj][2], acc[mi][nj][3],
                            av[mi][0], av[mi][1], av[mi][2], av[mi][3],
                            bv[nj][0], bv[nj][1]);
        }
        __syncthreads();                 // all warps done reading this item's slots
        if (staged) {
            cp_wait0();                  // staged data had a full item of cover
            __syncthreads();
        }
    }

    // ---- epilogue: relu + fp16 store ----
#pragma unroll
    for (int mi = 0; mi < MI; mi++) {
        int row = wM * (MI * 16) + mi * 16 + gid;
        size_t base0 = (((size_t)od * HO + oh) * WO + ow0 + row) * COUT;
        size_t base1 = base0 + 8 * COUT;      // row + 8
#pragma unroll
        for (int nj = 0; nj < NJ; nj++) {
            int col = wN * 32 + nj * 8 + tig * 2;
            float v00 = fmaxf(acc[mi][nj][0], 0.f);
            float v01 = fmaxf(acc[mi][nj][1], 0.f);
            float v10 = fmaxf(acc[mi][nj][2], 0.f);
            float v11 = fmaxf(acc[mi][nj][3], 0.f);
            __half2 p0 = __floats2half2_rn(v00, v01);
            __half2 p1 = __floats2half2_rn(v10, v11);
            *(uint32_t*)(out + base0 + col) = *(uint32_t*)&p0;
            *(uint32_t*)(out + base1 + col) = *(uint32_t*)&p1;
        }
    }
}

// ---------------- K5: conv3d 32->1 (no relu), smem-tiled, fp16 input ----------------
__global__ void __launch_bounds__(256)
k_reg2(const float* __restrict__ w2)
{
    __shared__ float ws_t[27 * 32];                 // [k27][ic32]
    __shared__ __half tile[10][34][32];             // [zh][zw][c] fp16
    int tx = threadIdx.x & 31;
    int ty = threadIdx.x >> 5;
    int tid = threadIdx.x;
    for (int i = tid; i < 864; i += 256) {
        int ic = i / 27, k = i % 27;
        ws_t[k * 32 + ic] = w2[i];
    }

    int ow0 = blockIdx.x * 32;
    int oh0 = blockIdx.y * 8;
    int od  = blockIdx.z;
    int ow = ow0 + tx, oh = oh0 + ty;

    float acc = 0.f;
    for (int kd = 0; kd < 3; kd++) {
        int zd = od + kd - 1;
        if (zd < 0 || zd >= DSLICE) continue;
        __syncthreads();
        // stage 10x34x32 fp16 plane (4 chunks of 8 halves per pixel)
        for (int i = tid; i < 10 * 34 * 4; i += 256) {
            int g  = i & 3;
            int zw = (i >> 2) % 34 + ow0 - 1;
            int zh = (i >> 2) / 34 + oh0 - 1;
            bool v = (zw >= 0 && zw < WO && zh >= 0 && zh < HO);
            int zwc = v ? zw : 0, zhc = v ? zh : 0;
            const __half* src = g_x2 + (((size_t)zd * HO + zhc) * WO + zwc) * C3 + g * 8;
            cp_async16(smem_u32(&tile[(i >> 2) / 34][(i >> 2) % 34][g * 8]), src, v);
        }
        cp_commit();
        cp_wait0();
        __syncthreads();

#pragma unroll
        for (int kh = 0; kh < 3; kh++) {
#pragma unroll
            for (int kw = 0; kw < 3; kw++) {
                int k = kd * 9 + kh * 3 + kw;
                const uint4* p = (const uint4*)&tile[ty + kh][tx + kw][0];
                const float* wv = &ws_t[k * 32];
#pragma unroll
                for (int g = 0; g < 4; g++) {
                    float f[8];
                    h8_to_f8(p[g], f);
#pragma unroll
                    for (int q = 0; q < 8; q++)
                        acc += f[q] * wv[g * 8 + q];
                }
            }
        }
    }
    g_x3[((size_t)od * HO + oh) * WO + ow] = acc;
}

// ---------------- K6: D-resize 4->8 + softmax + expectation ----------------
__global__ void k_final(float* __restrict__ outp)
{
    int pos = blockIdx.x * 256 + threadIdx.x;
    float v[4];
#pragma unroll
    for (int d = 0; d < 4; d++) v[d] = g_x3[(size_t)d * (HO * WO) + pos];

    float y[8];
#pragma unroll
    for (int o = 0; o < 8; o++) {
        float s = 0.5f * o - 0.25f;
        int j0 = max(0, (int)ceilf(s - 1.f));
        int j1 = min(3, (int)floorf(s + 1.f));
        float acc = 0.f, wsum = 0.f;
        for (int j = j0; j <= j1; j++) {
            float w = fmaxf(1.f - fabsf(s - (float)j), 0.f);
            acc += w * v[j]; wsum += w;
        }
        y[o] = acc / wsum;
    }
    float m = y[0];
#pragma unroll
    for (int o = 1; o < 8; o++) m = fmaxf(m, y[o]);
    float esum = 0.f, dsum = 0.f;
#pragma unroll
    for (int o = 0; o < 8; o++) {
        float e = expf(y[o] - m);
        esum += e;
        dsum += e * (float)o;
    }
    outp[pos] = dsum / esum;
}

// ---------------- host launch ----------------
extern "C" void kernel_launch(void* const* d_in, const int* in_sizes, int n_in,
                              void* d_out, int out_size)
{
    const float* cams[4] = { (const float*)d_in[0], (const float*)d_in[1],
                             (const float*)d_in[2], (const float*)d_in[3] };
    const float* grids    = (const float*)d_in[4];
    const float* w_feat   = (const float*)d_in[5];
    const float* w_fusion = (const float*)d_in[6];
    const float* w_reg1   = (const float*)d_in[7];
    const float* w_reg2   = (const float*)d_in[8];
    float* out = (float*)d_out;

    __half *p_wB1, *p_wB2, *p_costs, *p_x1, *p_x2;
    cudaGetSymbolAddress((void**)&p_wB1,   g_wB1);
    cudaGetSymbolAddress((void**)&p_wB2,   g_wB2);
    cudaGetSymbolAddress((void**)&p_costs, g_costs);
    cudaGetSymbolAddress((void**)&p_x1,    g_x1);
    cudaGetSymbolAddress((void**)&p_x2,    g_x2);

    // 2 A slots + 2 B slots (fp16)
    const int SMEM1 = 2 * 130 * PK1 * 2 + 2 * C2 * PK1 * 2;   // 70720 + 34816 = 105536 -> 2 CTAs
    const int SMEM2 = 2 * 130 * PK2 * 2 + 2 * C3 * PK2 * 2;   // 37440 +  9216 =  46656 -> 4 CTAs
    cudaFuncSetAttribute((const void*)k_conv3d_mma<CF, C2, 4, 2>,
                         cudaFuncAttributeMaxDynamicSharedMemorySize, SMEM1);
    cudaFuncSetAttribute((const void*)k_conv3d_mma<C2, C3, 2, 1>,
                         cudaFuncAttributeMaxDynamicSharedMemorySize, SMEM2);

    // 1: feature extraction + weight prep (fused)
    k_feat4w<<<dim3(FW / 16, FH / 16, 5), dim3(16, 16)>>>(
        cams[0], cams[1], cams[2], cams[3], w_feat, w_fusion, w_reg1);

    // 2: plane sweep warp (fp16 path, 2 d per thread)
    k_warp<<<dim3(FH * FW / 64, 2, CAMS), 256>>>(grids);

    // 3: antialiased resize -> fp16 cost volume
    k_resize<<<dim3(HO * WO / 64, DSLICE, CAMS), 256>>>();

    // 4: conv1 (profiled launch)  5: conv2 — fp16, A+B double-buffered
    k_conv3d_mma<CF, C2, 4, 2><<<dim3(WO / 128, HO, DSLICE), 128, SMEM1>>>(p_costs, p_wB1, p_x1);
    k_conv3d_mma<C2, C3, 2, 1><<<dim3(WO / 128, HO, DSLICE), 128, SMEM2>>>(p_x1, p_wB2, p_x2);

    // 6: squeeze conv (fp16 input)
    k_reg2<<<dim3(WO / 32, HO / 8, DSLICE), 256>>>(w_reg2);

    // 7: disparity regression
    k_final<<<(HO * WO) / 256, 256>>>(out);
}

// round 16
// speedup vs baseline: 3.7124x; 1.0685x over previous
#include <cuda_runtime.h>
#include <cuda_fp16.h>
#include <cstdint>
#include <math.h>

// ---------------- problem constants ----------------
#define CAMS   4
#define DSLICE 4      // D = NDISP/2
#define NDISP  8
#define IH     640
#define IW     1280
#define FH     320
#define FW     640
#define C1     32
#define HO     256
#define WO     256
#define CF     128    // fused cost channels
#define C2     64
#define C3     32

#define PK1    (CF + 8)    // padded K (elements) conv1
#define PK2    (C2 + 8)    // padded K conv2

// ---------------- scratch (static device memory; no allocs) ----------------
__device__ __half g_feat [(size_t)CAMS*FH*FW*C1];             // fp16 [cam][y][x][c]
__device__ __half g_warp [(size_t)CAMS*DSLICE*FH*FW*C1];      // fp16 [cam][d][y][x][c]
__device__ __half g_costs[(size_t)DSLICE*HO*WO*CF];           // fp16 cost volume [d][h][w][c]
__device__ __half g_x1   [(size_t)DSLICE*HO*WO*C2];           // fp16
__device__ __half g_x2   [(size_t)DSLICE*HO*WO*C3];           // fp16
__device__ float  g_x3   [(size_t)DSLICE*HO*WO];
__device__ __half g_wB1  [27*C2*PK1];   // conv1 weights fp16 [tap][n][PK1]
__device__ __half g_wB2  [27*C3*PK2];   // conv2 weights fp16 [tap][n][PK2]

// =====================================================================
// helpers
// =====================================================================
__device__ __forceinline__ uint32_t smem_u32(const void* p) {
    uint32_t a;
    asm("{ .reg .u64 t; cvta.to.shared.u64 t, %1; cvt.u32.u64 %0, t; }" : "=r"(a) : "l"(p));
    return a;
}
__device__ __forceinline__ void ldsm_x4(uint32_t& r0, uint32_t& r1, uint32_t& r2, uint32_t& r3,
                                        uint32_t addr)
{
    asm volatile("ldmatrix.sync.aligned.m8n8.x4.shared.b16 {%0,%1,%2,%3}, [%4];"
                 : "=r"(r0), "=r"(r1), "=r"(r2), "=r"(r3) : "r"(addr));
}
__device__ __forceinline__ void cp_async16(uint32_t dst, const void* src, bool valid) {
    int sz = valid ? 16 : 0;
    asm volatile("cp.async.cg.shared.global [%0], [%1], 16, %2;"
                 :: "r"(dst), "l"(src), "r"(sz) : "memory");
}
__device__ __forceinline__ void cp_commit() {
    asm volatile("cp.async.commit_group;" ::: "memory");
}
__device__ __forceinline__ void cp_wait0() {
    asm volatile("cp.async.wait_group 0;" ::: "memory");
}
__device__ __forceinline__ void mma_f16(float& d0, float& d1, float& d2, float& d3,
                                        uint32_t a0, uint32_t a1, uint32_t a2, uint32_t a3,
                                        uint32_t b0, uint32_t b1)
{
    asm volatile(
        "mma.sync.aligned.m16n8k16.row.col.f32.f16.f16.f32 "
        "{%0,%1,%2,%3}, {%4,%5,%6,%7}, {%8,%9}, {%0,%1,%2,%3};"
        : "+f"(d0), "+f"(d1), "+f"(d2), "+f"(d3)
        : "r"(a0), "r"(a1), "r"(a2), "r"(a3), "r"(b0), "r"(b1));
}
// 8 halves (uint4) -> 8 floats
__device__ __forceinline__ void h8_to_f8(uint4 v, float* f) {
    float2 t;
    t = __half22float2(*(__half2*)&v.x); f[0] = t.x; f[1] = t.y;
    t = __half22float2(*(__half2*)&v.y); f[2] = t.x; f[3] = t.y;
    t = __half22float2(*(__half2*)&v.z); f[4] = t.x; f[5] = t.y;
    t = __half22float2(*(__half2*)&v.w); f[6] = t.x; f[7] = t.y;
}
__device__ __forceinline__ uint4 f8_to_h8(const float* f) {
    uint4 v;
    __half2 t;
    t = __floats2half2_rn(f[0], f[1]); v.x = *(uint32_t*)&t;
    t = __floats2half2_rn(f[2], f[3]); v.y = *(uint32_t*)&t;
    t = __floats2half2_rn(f[4], f[5]); v.z = *(uint32_t*)&t;
    t = __floats2half2_rn(f[6], f[7]); v.w = *(uint32_t*)&t;
    return v;
}

// ---------------- K1: conv2d 3->32 s2 + relu (grid.z<4) fused with weight prep (grid.z==4) ----
__global__ void k_feat4w(const float* __restrict__ c0, const float* __restrict__ c1,
                         const float* __restrict__ c2, const float* __restrict__ c3,
                         const float* __restrict__ w,
                         const float* __restrict__ w_fusion, const float* __restrict__ w_reg1)
{
    int tid = threadIdx.y * 16 + threadIdx.x;
    int zi  = blockIdx.z;

    if (zi == 4) {
        int idx0   = (blockIdx.y * (FW / 16) + blockIdx.x) * 256 + tid;
        int stride = (FW / 16) * (FH / 16) * 256;
        for (int i = idx0; i < 27 * C2 * CF; i += stride) {
            int k = i % CF;
            int n = (i / CF) % C2;
            int t = i / (CF * C2);
            int kw = t % 3, kh = (t / 3) % 3, kd = t / 9;
            float v = w_fusion[((((size_t)n * CF + k) * 3 + kd) * 3 + kh) * 3 + kw];
            g_wB1[((size_t)t * C2 + n) * PK1 + k] = __float2half(v);
        }
        for (int i = idx0; i < 27 * C3 * C2; i += stride) {
            int k = i % C2;
            int n = (i / C2) % C3;
            int t = i / (C2 * C3);
            int kw = t % 3, kh = (t / 3) % 3, kd = t / 9;
            float v = w_reg1[((((size_t)n * C2 + k) * 3 + kd) * 3 + kh) * 3 + kw];
            g_wB2[((size_t)t * C3 + n) * PK2 + k] = __float2half(v);
        }
        return;
    }

    __shared__ float ws[27 * 32];
    for (int i = tid; i < 864; i += 256) {
        int k = i >> 5, oc = i & 31;
        ws[i] = w[oc * 27 + k];
    }
    __syncthreads();

    const float* cam = (zi == 0) ? c0 : (zi == 1) ? c1 : (zi == 2) ? c2 : c3;
    int ow = blockIdx.x * 16 + threadIdx.x;
    int oh = blockIdx.y * 16 + threadIdx.y;

    float v[27];
#pragma unroll
    for (int ic = 0; ic < 3; ic++)
#pragma unroll
        for (int kh = 0; kh < 3; kh++)
#pragma unroll
            for (int kw = 0; kw < 3; kw++) {
                int iy = 2 * oh + kh - 1;
                int ix = 2 * ow + kw - 1;
                float t = 0.f;
                if (iy >= 0 && iy < IH && ix >= 0 && ix < IW)
                    t = cam[(size_t)ic * IH * IW + (size_t)iy * IW + ix];
                v[ic * 9 + kh * 3 + kw] = t;
            }

    float4 acc[8];
#pragma unroll
    for (int q = 0; q < 8; q++) acc[q] = make_float4(0.f, 0.f, 0.f, 0.f);
    const float4* ws4 = (const float4*)ws;
#pragma unroll
    for (int k = 0; k < 27; k++) {
        float vv = v[k];
#pragma unroll
        for (int q = 0; q < 8; q++) {
            float4 wv = ws4[k * 8 + q];
            acc[q].x += vv * wv.x;  acc[q].y += vv * wv.y;
            acc[q].z += vv * wv.z;  acc[q].w += vv * wv.w;
        }
    }
    __half* o = g_feat + ((size_t)zi * FH * FW + (size_t)oh * FW + ow) * C1;
#pragma unroll
    for (int q = 0; q < 4; q++) {
        float f[8];
        f[0] = fmaxf(acc[2*q].x, 0.f);   f[1] = fmaxf(acc[2*q].y, 0.f);
        f[2] = fmaxf(acc[2*q].z, 0.f);   f[3] = fmaxf(acc[2*q].w, 0.f);
        f[4] = fmaxf(acc[2*q+1].x, 0.f); f[5] = fmaxf(acc[2*q+1].y, 0.f);
        f[6] = fmaxf(acc[2*q+1].z, 0.f); f[7] = fmaxf(acc[2*q+1].w, 0.f);
        *(uint4*)(o + q * 8) = f8_to_h8(f);
    }
}

// ---------------- K2: grid_sample fp16, 4 lanes/pixel, 2 d-slices per thread ----------------
__global__ void __launch_bounds__(256)
k_warp(const float* __restrict__ grids)
{
    int tid = threadIdx.x;
    int c   = tid & 3;           // 8-half chunk
    int pid = tid >> 2;          // pixel within block (0..63)
    int pos = blockIdx.x * 64 + pid;
    int d0  = blockIdx.y;
    int cam = blockIdx.z;
    int y = pos / FW, x = pos % FW;

    const __half* fb = g_feat + (size_t)cam * FH * FW * C1 + c * 8;

#pragma unroll
    for (int s = 0; s < 2; s++) {
        int d = d0 + s * 2;
        const float* g = grids + ((((size_t)cam * DSLICE + d) * FH + y) * FW + x) * 2;
        float fx = (g[0] + 1.f) * (FW * 0.5f) - 0.5f;
        float fy = (g[1] + 1.f) * (FH * 0.5f) - 0.5f;
        float x0f = floorf(fx), y0f = floorf(fy);
        float wx = fx - x0f,   wy = fy - y0f;
        int x0 = (int)x0f, y0 = (int)y0f;
        int x1 = x0 + 1,   y1 = y0 + 1;
        float vx0 = (x0 >= 0 && x0 < FW) ? 1.f : 0.f;
        float vx1 = (x1 >= 0 && x1 < FW) ? 1.f : 0.f;
        float vy0 = (y0 >= 0 && y0 < FH) ? 1.f : 0.f;
        float vy1 = (y1 >= 0 && y1 < FH) ? 1.f : 0.f;
        float w00 = (1.f - wx) * (1.f - wy) * vx0 * vy0;
        float w01 = wx * (1.f - wy) * vx1 * vy0;
        float w10 = (1.f - wx) * wy * vx0 * vy1;
        float w11 = wx * wy * vx1 * vy1;
        int x0c = min(max(x0, 0), FW - 1), x1c = min(max(x1, 0), FW - 1);
        int y0c = min(max(y0, 0), FH - 1), y1c = min(max(y1, 0), FH - 1);

        uint4 ra = *(const uint4*)(fb + ((size_t)y0c * FW + x0c) * C1);
        uint4 rb = *(const uint4*)(fb + ((size_t)y0c * FW + x1c) * C1);
        uint4 re = *(const uint4*)(fb + ((size_t)y1c * FW + x0c) * C1);
        uint4 rf = *(const uint4*)(fb + ((size_t)y1c * FW + x1c) * C1);
        float a[8], b[8], e[8], f[8], r[8];
        h8_to_f8(ra, a); h8_to_f8(rb, b); h8_to_f8(re, e); h8_to_f8(rf, f);
#pragma unroll
        for (int q = 0; q < 8; q++)
            r[q] = w00 * a[q] + w01 * b[q] + w10 * e[q] + w11 * f[q];
        *(uint4*)(g_warp + ((size_t)(cam * DSLICE + d) * FH * FW + pos) * C1 + c * 8) = f8_to_h8(r);
    }
}

// ---------------- K3: antialiased resize fp16, 4 lanes/pixel ----------------
__global__ void __launch_bounds__(256)
k_resize()
{
    int tid  = threadIdx.x;
    int c    = tid & 3;
    int pid  = tid >> 2;
    int opos = blockIdx.x * 64 + pid;
    int ho   = opos >> 8;
    int wo   = opos & 255;
    int d    = blockIdx.y;
    int cam  = blockIdx.z;

    float sy = (ho + 0.5f) * 1.25f - 0.5f;
    int jy0 = max((int)ceilf(sy - 1.25f), 0);
    int jy1 = min((int)floorf(sy + 1.25f), FH - 1);
    float wyv[4]; int ny = jy1 - jy0 + 1;
    float sumy = 0.f;
    for (int i = 0; i < ny; i++) {
        float w = fmaxf(1.f - fabsf(sy - (float)(jy0 + i)) * 0.8f, 0.f);
        wyv[i] = w; sumy += w;
    }
    for (int i = 0; i < ny; i++) wyv[i] /= sumy;

    float sx = (wo + 0.5f) * 2.5f - 0.5f;
    int jx0 = max((int)ceilf(sx - 2.5f), 0);
    int jx1 = min((int)floorf(sx + 2.5f), FW - 1);
    float wxv[6]; int nx = jx1 - jx0 + 1;
    float sumx = 0.f;
    for (int i = 0; i < nx; i++) {
        float w = fmaxf(1.f - fabsf(sx - (float)(jx0 + i)) * 0.4f, 0.f);
        wxv[i] = w; sumx += w;
    }
    for (int i = 0; i < nx; i++) wxv[i] /= sumx;

    float acc[8];
#pragma unroll
    for (int q = 0; q < 8; q++) acc[q] = 0.f;
    const __half* base = g_warp + (size_t)(cam * DSLICE + d) * FH * FW * C1 + c * 8;
    for (int iy = 0; iy < ny; iy++) {
        const __half* rowb = base + (size_t)(jy0 + iy) * FW * C1;
        for (int ix = 0; ix < nx; ix++) {
            float wgt = wyv[iy] * wxv[ix];
            float t[8];
            h8_to_f8(*(const uint4*)(rowb + (size_t)(jx0 + ix) * C1), t);
#pragma unroll
            for (int q = 0; q < 8; q++) acc[q] += wgt * t[q];
        }
    }
    size_t obase = (((size_t)d * HO + ho) * WO + wo) * CF + cam * C1 + c * 8;
    *(uint4*)(g_costs + obase) = f8_to_h8(acc);
}

// ---------------- K4: conv3d 3x3x3 pad1 + relu, fp16 mma + ldmatrix -------------------------
// 128 threads / 4 warps, single A plane + single B tap -> 52.8/23.3 KB -> 4 CTAs/SM.
// Fragment loads via ldmatrix.x4 (4x fewer smem instructions than scalar LDS).
// conv1: MI=4, NWN=2 (warp M64xN32). conv2: MI=2, NWN=1 (warp M32xN32).
template<int CIN, int COUT, int MI, int NWN>
__global__ void __launch_bounds__(128)
k_conv3d_mma(const __half* __restrict__ in, const __half* __restrict__ wB,
             __half* __restrict__ out)
{
    constexpr int NT   = 128;
    constexpr int PK   = CIN + 8;
    constexpr int PKB  = PK * 2;             // bytes per smem row
    constexpr int SA   = 130 * PKB;          // A plane bytes
    constexpr int TB   = COUT * PKB;         // B tap bytes
    constexpr int NJ   = (COUT / NWN) / 8;   // 4
    constexpr int NP   = NJ / 2;             // B ldmatrix pairs
    constexpr int KST  = CIN / 16;           // k-steps per item
    constexpr int CH   = CIN / 8;            // 16B chunks per A row

    extern __shared__ char dsm[];
    const uint32_t sBase = smem_u32(dsm);
    const uint32_t sA = sBase;               // [A | B]
    const uint32_t sB = sBase + SA;

    int tid  = threadIdx.x;
    int wid  = tid >> 5, lane = tid & 31;
    int gid  = lane >> 2, tig = lane & 3;
    int wM   = wid / NWN;
    int wN   = wid % NWN;
    int ow0  = blockIdx.x * 128;
    int oh   = blockIdx.y, od = blockIdx.z;

    // ldmatrix per-lane row offsets
    // A x4 (m16 x k16): lanes 0-15 -> rows 0-15 chunk0; lanes 16-31 -> rows 0-15 chunk1
    uint32_t aLane = (uint32_t)(lane & 15) * PKB + (uint32_t)(lane >> 4) * 16;
    // B x4 (two n8 x k16 tiles): lanes 0-7 n0-7/chunk0, 8-15 n0-7/chunk1,
    //                            16-23 n8-15/chunk0, 24-31 n8-15/chunk1
    uint32_t bLane = ((uint32_t)(lane & 7) + (uint32_t)(lane >> 4) * 8) * PKB
                   + (uint32_t)((lane >> 3) & 1) * 16;

    // ---- build valid (kd,kh) list ----
    int zdv[9], zhv[9], t9v[9];
    int nv = 0;
    for (int kd = 0; kd < 3; kd++) {
        int zd = od + kd - 1;
        if (zd < 0 || zd >= DSLICE) continue;
        for (int kh = 0; kh < 3; kh++) {
            int zh = oh + kh - 1;
            if (zh < 0 || zh >= HO) continue;
            zdv[nv] = zd; zhv[nv] = zh; t9v[nv] = kd * 3 + kh;
            nv++;
        }
    }
    int nitems = nv * 3;

    float acc[MI][NJ][4];
#pragma unroll
    for (int mi = 0; mi < MI; mi++)
#pragma unroll
        for (int nj = 0; nj < NJ; nj++)
#pragma unroll
            for (int cc = 0; cc < 4; cc++) acc[mi][nj][cc] = 0.f;

    auto stage_A = [&](int ai) {
        size_t inoff = ((size_t)zdv[ai] * HO + zhv[ai]) * WO * CIN;
        for (int i = tid; i < 130 * CH; i += NT) {
            int r = i / CH, g = i % CH;
            int p = ow0 - 1 + r;
            bool v = (p >= 0 && p < WO);
            int pc = v ? p : 0;
            cp_async16(sA + (uint32_t)r * PKB + g * 16,
                       in + inoff + (size_t)pc * CIN + g * 8, v);
        }
    };
    auto stage_B = [&](int j) {
        int t = t9v[j / 3] * 3 + (j % 3);
        const char* src = (const char*)(wB + (size_t)t * COUT * PK);
        for (int i = tid; i < TB / 16; i += NT)
            cp_async16(sB + i * 16, src + i * 16, true);
    };

    for (int j = 0; j < nitems; j++) {
        if (j % 3 == 0) stage_A(j / 3);
        stage_B(j);
        cp_commit();
        cp_wait0();
        __syncthreads();

        int q = j % 3;
        uint32_t aB0 = sA + (uint32_t)(q + wM * (MI * 16)) * PKB + aLane;
        uint32_t bB0 = sB + (uint32_t)(wN * 32) * PKB + bLane;
#pragma unroll
        for (int ks = 0; ks < KST; ks++) {
            uint32_t ko = (uint32_t)ks * 32;
            uint32_t av[MI][4], bv[NJ][2];
#pragma unroll
            for (int mi = 0; mi < MI; mi++)
                ldsm_x4(av[mi][0], av[mi][1], av[mi][2], av[mi][3],
                        aB0 + (uint32_t)(mi * 16) * PKB + ko);
#pragma unroll
            for (int p = 0; p < NP; p++)
                ldsm_x4(bv[2*p][0], bv[2*p][1], bv[2*p+1][0], bv[2*p+1][1],
                        bB0 + (uint32_t)(p * 16) * PKB + ko);
#pragma unroll
            for (int nj = 0; nj < NJ; nj++)
#pragma unroll
                for (int mi = 0; mi < MI; mi++)
                    mma_f16(acc[mi][nj][0], acc[mi][nj][1], acc[mi][nj][2], acc[mi][nj][3],
                            av[mi][0], av[mi][1], av[mi][2], av[mi][3],
                            bv[nj][0], bv[nj][1]);
        }
        __syncthreads();
    }

    // ---- epilogue: relu + fp16 store ----
#pragma unroll
    for (int mi = 0; mi < MI; mi++) {
        int row = wM * (MI * 16) + mi * 16 + gid;
        size_t base0 = (((size_t)od * HO + oh) * WO + ow0 + row) * COUT;
        size_t base1 = base0 + 8 * COUT;      // row + 8
#pragma unroll
        for (int nj = 0; nj < NJ; nj++) {
            int col = wN * 32 + nj * 8 + tig * 2;
            float v00 = fmaxf(acc[mi][nj][0], 0.f);
            float v01 = fmaxf(acc[mi][nj][1], 0.f);
            float v10 = fmaxf(acc[mi][nj][2], 0.f);
            float v11 = fmaxf(acc[mi][nj][3], 0.f);
            __half2 p0 = __floats2half2_rn(v00, v01);
            __half2 p1 = __floats2half2_rn(v10, v11);
            *(uint32_t*)(out + base0 + col) = *(uint32_t*)&p0;
            *(uint32_t*)(out + base1 + col) = *(uint32_t*)&p1;
        }
    }
}

// ---------------- K5: conv3d 32->1 (no relu), smem-tiled, fp16 input ----------------
__global__ void __launch_bounds__(256)
k_reg2(const float* __restrict__ w2)
{
    __shared__ float ws_t[27 * 32];                 // [k27][ic32]
    __shared__ __half tile[10][34][32];             // [zh][zw][c] fp16
    int tx = threadIdx.x & 31;
    int ty = threadIdx.x >> 5;
    int tid = threadIdx.x;
    for (int i = tid; i < 864; i += 256) {
        int ic = i / 27, k = i % 27;
        ws_t[k * 32 + ic] = w2[i];
    }

    int ow0 = blockIdx.x * 32;
    int oh0 = blockIdx.y * 8;
    int od  = blockIdx.z;
    int ow = ow0 + tx, oh = oh0 + ty;

    float acc = 0.f;
    for (int kd = 0; kd < 3; kd++) {
        int zd = od + kd - 1;
        if (zd < 0 || zd >= DSLICE) continue;
        __syncthreads();
        for (int i = tid; i < 10 * 34 * 4; i += 256) {
            int g  = i & 3;
            int zw = (i >> 2) % 34 + ow0 - 1;
            int zh = (i >> 2) / 34 + oh0 - 1;
            bool v = (zw >= 0 && zw < WO && zh >= 0 && zh < HO);
            int zwc = v ? zw : 0, zhc = v ? zh : 0;
            const __half* src = g_x2 + (((size_t)zd * HO + zhc) * WO + zwc) * C3 + g * 8;
            cp_async16(smem_u32(&tile[(i >> 2) / 34][(i >> 2) % 34][g * 8]), src, v);
        }
        cp_commit();
        cp_wait0();
        __syncthreads();

#pragma unroll
        for (int kh = 0; kh < 3; kh++) {
#pragma unroll
            for (int kw = 0; kw < 3; kw++) {
                int k = kd * 9 + kh * 3 + kw;
                const uint4* p = (const uint4*)&tile[ty + kh][tx + kw][0];
                const float* wv = &ws_t[k * 32];
#pragma unroll
                for (int g = 0; g < 4; g++) {
                    float f[8];
                    h8_to_f8(p[g], f);
#pragma unroll
                    for (int q = 0; q < 8; q++)
                        acc += f[q] * wv[g * 8 + q];
                }
            }
        }
    }
    g_x3[((size_t)od * HO + oh) * WO + ow] = acc;
}

// ---------------- K6: D-resize 4->8 + softmax + expectation ----------------
__global__ void k_final(float* __restrict__ outp)
{
    int pos = blockIdx.x * 256 + threadIdx.x;
    float v[4];
#pragma unroll
    for (int d = 0; d < 4; d++) v[d] = g_x3[(size_t)d * (HO * WO) + pos];

    float y[8];
#pragma unroll
    for (int o = 0; o < 8; o++) {
        float s = 0.5f * o - 0.25f;
        int j0 = max(0, (int)ceilf(s - 1.f));
        int j1 = min(3, (int)floorf(s + 1.f));
        float acc = 0.f, wsum = 0.f;
        for (int j = j0; j <= j1; j++) {
            float w = fmaxf(1.f - fabsf(s - (float)j), 0.f);
            acc += w * v[j]; wsum += w;
        }
        y[o] = acc / wsum;
    }
    float m = y[0];
#pragma unroll
    for (int o = 1; o < 8; o++) m = fmaxf(m, y[o]);
    float esum = 0.f, dsum = 0.f;
#pragma unroll
    for (int o = 0; o < 8; o++) {
        float e = expf(y[o] - m);
        esum += e;
        dsum += e * (float)o;
    }
    outp[pos] = dsum / esum;
}

// ---------------- host launch ----------------
extern "C" void kernel_launch(void* const* d_in, const int* in_sizes, int n_in,
                              void* d_out, int out_size)
{
    const float* cams[4] = { (const float*)d_in[0], (const float*)d_in[1],
                             (const float*)d_in[2], (const float*)d_in[3] };
    const float* grids    = (const float*)d_in[4];
    const float* w_feat   = (const float*)d_in[5];
    const float* w_fusion = (const float*)d_in[6];
    const float* w_reg1   = (const float*)d_in[7];
    const float* w_reg2   = (const float*)d_in[8];
    float* out = (float*)d_out;

    __half *p_wB1, *p_wB2, *p_costs, *p_x1, *p_x2;
    cudaGetSymbolAddress((void**)&p_wB1,   g_wB1);
    cudaGetSymbolAddress((void**)&p_wB2,   g_wB2);
    cudaGetSymbolAddress((void**)&p_costs, g_costs);
    cudaGetSymbolAddress((void**)&p_x1,    g_x1);
    cudaGetSymbolAddress((void**)&p_x2,    g_x2);

    // single A plane + single B tap (fp16)
    const int SMEM1 = 130 * PK1 * 2 + C2 * PK1 * 2;   // 35360 + 17408 = 52768 -> 4 CTAs/SM
    const int SMEM2 = 130 * PK2 * 2 + C3 * PK2 * 2;   // 18720 +  4608 = 23328
    cudaFuncSetAttribute((const void*)k_conv3d_mma<CF, C2, 4, 2>,
                         cudaFuncAttributeMaxDynamicSharedMemorySize, SMEM1);
    cudaFuncSetAttribute((const void*)k_conv3d_mma<C2, C3, 2, 1>,
                         cudaFuncAttributeMaxDynamicSharedMemorySize, SMEM2);

    // 1: feature extraction + weight prep (fused)
    k_feat4w<<<dim3(FW / 16, FH / 16, 5), dim3(16, 16)>>>(
        cams[0], cams[1], cams[2], cams[3], w_feat, w_fusion, w_reg1);

    // 2: plane sweep warp (fp16 path, 2 d per thread)
    k_warp<<<dim3(FH * FW / 64, 2, CAMS), 256>>>(grids);

    // 3: antialiased resize -> fp16 cost volume
    k_resize<<<dim3(HO * WO / 64, DSLICE, CAMS), 256>>>();

    // 4: conv1 (profiled launch)  5: conv2 — fp16 + ldmatrix, 4 CTAs/SM
    k_conv3d_mma<CF, C2, 4, 2><<<dim3(WO / 128, HO, DSLICE), 128, SMEM1>>>(p_costs, p_wB1, p_x1);
    k_conv3d_mma<C2, C3, 2, 1><<<dim3(WO / 128, HO, DSLICE), 128, SMEM2>>>(p_x1, p_wB2, p_x2);

    // 6: squeeze conv (fp16 input)
    k_reg2<<<dim3(WO / 32, HO / 8, DSLICE), 256>>>(w_reg2);

    // 7: disparity regression
    k_final<<<(HO * WO) / 256, 256>>>(out);
}